// round 1
// baseline (speedup 1.0000x reference)
#include <cuda_runtime.h>
#include <cstdint>
#include <math.h>

#define NN 100000
#define NE 600000
#define DD 128

typedef unsigned long long u64;

// ---------------- device scratch (allocation-free rule: __device__ globals) ----------
__device__ float g_f[NN * DD];       // feat @ W_tran^T
__device__ float g_geo[NN * DD];     // geo mean agg (sum, then normalized in place)
__device__ float g_trans[NN * DD];   // weighted sum agg
__device__ float g_cat[NN * DD];     // cat mean agg
__device__ float g_cnt_geo[NN];
__device__ float g_cnt_cat[NN];
__device__ float g_wsum[3];          // sum over nodes of h @ w2^T, per relation
__device__ float g_beta[3];

// ---------------- f32x2 packed-FMA helpers (SASS FFMA2: 2x FFMA throughput) ---------
__device__ __forceinline__ u64 pack2(float x) {
    u64 r; asm("mov.b64 %0, {%1, %1};" : "=l"(r) : "f"(x)); return r;
}
__device__ __forceinline__ void ffma2(u64& d, u64 a, u64 b) {
    asm("fma.rn.f32x2 %0, %1, %2, %0;" : "+l"(d) : "l"(a), "l"(b));
}
__device__ __forceinline__ float2 unpack2(u64 v) {
    float2 f; asm("mov.b64 {%0, %1}, %2;" : "=f"(f.x), "=f"(f.y) : "l"(v)); return f;
}

// Stage a [128 x 128] row-major weight block into smem in "paired-transposed" layout:
// Ws[(k*32 + l)*4 + c] where lane l owns outputs j = {2l, 2l+1, 64+2l, 64+2l+1} (c=0..3).
// Read back as ulonglong2 -> one LDS.128 per lane per k, conflict-free, each half is an
// f32x2 multiplicand pair.
__device__ __forceinline__ void stage_w128(float* Ws, const float* __restrict__ Wsrc,
                                           int tid, int nthreads) {
    for (int idx = tid; idx < DD * DD; idx += nthreads) {
        int j = idx >> 7, k = idx & 127;
        int l, c;
        if (j < 64) { l = j >> 1; c = j & 1; }
        else        { l = (j - 64) >> 1; c = 2 + ((j - 64) & 1); }
        Ws[(k * 32 + l) * 4 + c] = Wsrc[idx];
    }
}

// ---------------- kernel 0: zero accumulators -----------------------------------------
__global__ void zero_kernel() {
    int i = blockIdx.x * blockDim.x + threadIdx.x;
    int stride = gridDim.x * blockDim.x;
    float4 z = make_float4(0.f, 0.f, 0.f, 0.f);
    const int n4 = NN * DD / 4;
    for (int k = i; k < n4; k += stride) {
        ((float4*)g_geo)[k] = z;
        ((float4*)g_cat)[k] = z;
        ((float4*)g_trans)[k] = z;
    }
    for (int k = i; k < NN; k += stride) { g_cnt_geo[k] = 0.f; g_cnt_cat[k] = 0.f; }
    if (i < 3) g_wsum[i] = 0.f;
}

// ---------------- kernel 1: f = feat @ W_tran^T ---------------------------------------
// Block: 256 threads (8 warps), each warp processes 4 nodes per iteration.
// smem: Ws 64KB (paired W layout) + Zs 32KB (z values pre-duplicated as f32x2).
__global__ __launch_bounds__(256) void gemm_f_kernel(const float* __restrict__ feat,
                                                     const float* __restrict__ W) {
    extern __shared__ char smem[];
    float* Ws = (float*)smem;                  // 65536 B
    u64* Zs = (u64*)(smem + 65536);            // 8 warps * 4 nodes * 128 * 8B = 32768 B
    int tid = threadIdx.x;
    stage_w128(Ws, W, tid, 256);
    __syncthreads();

    const ulonglong2* Wv = (const ulonglong2*)Ws;
    int warp = tid >> 5, lane = tid & 31;
    u64* Zw = Zs + warp * 4 * DD;

    for (int base = blockIdx.x * 32 + warp * 4; base < NN; base += gridDim.x * 32) {
#pragma unroll
        for (int m = 0; m < 4; m++) {
            int n = base + m;
            float4 v = (n < NN) ? ((const float4*)feat)[n * 32 + lane]
                                : make_float4(0.f, 0.f, 0.f, 0.f);
            u64* zp = Zw + m * DD + lane * 4;
            zp[0] = pack2(v.x); zp[1] = pack2(v.y); zp[2] = pack2(v.z); zp[3] = pack2(v.w);
        }
        __syncwarp();

        u64 acc[4][2];
#pragma unroll
        for (int m = 0; m < 4; m++) { acc[m][0] = 0ull; acc[m][1] = 0ull; }

#pragma unroll 4
        for (int k = 0; k < DD; k++) {
            ulonglong2 wv = Wv[k * 32 + lane];
#pragma unroll
            for (int m = 0; m < 4; m++) {
                u64 zz = Zw[m * DD + k];
                ffma2(acc[m][0], zz, wv.x);
                ffma2(acc[m][1], zz, wv.y);
            }
        }

#pragma unroll
        for (int m = 0; m < 4; m++) {
            int n = base + m;
            if (n < NN) {
                float2 p0 = unpack2(acc[m][0]);   // out[2l], out[2l+1]
                float2 p1 = unpack2(acc[m][1]);   // out[64+2l], out[64+2l+1]
                ((float2*)g_f)[n * 64 + lane] = p0;
                ((float2*)g_f)[n * 64 + 32 + lane] = p1;
            }
        }
        __syncwarp();
    }
}

// ---------------- kernel 2: all three edge aggregations -------------------------------
// One warp per edge: 32 lanes read the 512B source row (float4 each), vector-RED into
// the destination row. rel 0=geo, 1=cat, 2=trans(weighted).
__global__ __launch_bounds__(256) void aggregate_kernel(
    const int* __restrict__ gs, const int* __restrict__ gd,
    const int* __restrict__ cs, const int* __restrict__ cd,
    const int* __restrict__ ts, const int* __restrict__ td,
    const float* __restrict__ tw) {
    long long gwid = (long long)blockIdx.x * (blockDim.x >> 5) + (threadIdx.x >> 5);
    int lane = threadIdx.x & 31;
    if (gwid >= 3LL * NE) return;
    int rel = (int)(gwid / NE);
    int e = (int)(gwid - (long long)rel * NE);

    int src, dst; float w = 1.f; float* base;
    if (rel == 0)      { src = gs[e]; dst = gd[e]; base = g_geo; }
    else if (rel == 1) { src = cs[e]; dst = cd[e]; base = g_cat; }
    else               { src = ts[e]; dst = td[e]; base = g_trans; w = tw[e]; }

    float4 v = ((const float4*)(g_f + (size_t)src * DD))[lane];
    if (rel == 2) { v.x *= w; v.y *= w; v.z *= w; v.w *= w; }

    float* p = base + (size_t)dst * DD + lane * 4;
    asm volatile("red.global.add.v4.f32 [%0], {%1,%2,%3,%4};"
                 :: "l"(p), "f"(v.x), "f"(v.y), "f"(v.z), "f"(v.w) : "memory");

    if (lane == 0) {
        if (rel == 0)      atomicAdd(&g_cnt_geo[dst], 1.0f);
        else if (rel == 1) atomicAdd(&g_cnt_cat[dst], 1.0f);
    }
}

// ---------------- kernel 3: normalize means in place ----------------------------------
__global__ void normalize_kernel() {
    int i = blockIdx.x * blockDim.x + threadIdx.x;
    if (i >= NN * DD / 4) return;
    int n = i >> 5;
    float ig = 1.f / fmaxf(g_cnt_geo[n], 1.f);
    float ic = 1.f / fmaxf(g_cnt_cat[n], 1.f);
    float4 g = ((float4*)g_geo)[i];
    g.x *= ig; g.y *= ig; g.z *= ig; g.w *= ig;
    ((float4*)g_geo)[i] = g;
    float4 c = ((float4*)g_cat)[i];
    c.x *= ic; c.y *= ic; c.z *= ic; c.w *= ic;
    ((float4*)g_cat)[i] = c;
}

// ---------------- kernel 4: attention GEMM + reduce -----------------------------------
// wsum[r] = sum_n sum_j w2[j] * tanh( W1[j,:] . z[n,r,:] + b1[j] )
// Decomposes over j-chunks of 128 -> grid.z = 4 chunks, grid.y = 3 relations.
// Same f32x2 microkernel as gemm_f; each block accumulates one partial scalar.
__global__ __launch_bounds__(256) void att_gemm_kernel(const float* __restrict__ W1,
                                                       const float* __restrict__ B1,
                                                       const float* __restrict__ W2) {
    extern __shared__ char smem[];
    float* Ws = (float*)smem;                         // 65536
    u64* Zs = (u64*)(smem + 65536);                   // 32768
    float* b1s = (float*)(smem + 65536 + 32768);      // 512
    float* w2s = b1s + 128;                           // 512
    __shared__ float s_part;

    int tid = threadIdx.x;
    int r = blockIdx.y, chunk = blockIdx.z;
    const float* zsrc = (r == 0) ? g_geo : (r == 1) ? g_trans : g_cat;

    stage_w128(Ws, W1 + (size_t)chunk * 128 * DD, tid, 256);
    if (tid < 128) { b1s[tid] = B1[chunk * 128 + tid]; w2s[tid] = W2[chunk * 128 + tid]; }
    if (tid == 0) s_part = 0.f;
    __syncthreads();

    const ulonglong2* Wv = (const ulonglong2*)Ws;
    int warp = tid >> 5, lane = tid & 31;
    u64* Zw = Zs + warp * 4 * DD;
    float psum = 0.f;

    for (int base = blockIdx.x * 32 + warp * 4; base < NN; base += gridDim.x * 32) {
#pragma unroll
        for (int m = 0; m < 4; m++) {
            int n = base + m;
            float4 v = (n < NN) ? ((const float4*)zsrc)[n * 32 + lane]
                                : make_float4(0.f, 0.f, 0.f, 0.f);
            u64* zp = Zw + m * DD + lane * 4;
            zp[0] = pack2(v.x); zp[1] = pack2(v.y); zp[2] = pack2(v.z); zp[3] = pack2(v.w);
        }
        __syncwarp();

        u64 acc[4][2];
#pragma unroll
        for (int m = 0; m < 4; m++) { acc[m][0] = 0ull; acc[m][1] = 0ull; }

#pragma unroll 4
        for (int k = 0; k < DD; k++) {
            ulonglong2 wv = Wv[k * 32 + lane];
#pragma unroll
            for (int m = 0; m < 4; m++) {
                u64 zz = Zw[m * DD + k];
                ffma2(acc[m][0], zz, wv.x);
                ffma2(acc[m][1], zz, wv.y);
            }
        }

#pragma unroll
        for (int m = 0; m < 4; m++) {
            int n = base + m;
            if (n < NN) {
                float2 a0 = unpack2(acc[m][0]);
                float2 a1 = unpack2(acc[m][1]);
                float h0 = tanhf(a0.x + b1s[2 * lane]);
                float h1 = tanhf(a0.y + b1s[2 * lane + 1]);
                float h2 = tanhf(a1.x + b1s[64 + 2 * lane]);
                float h3 = tanhf(a1.y + b1s[64 + 2 * lane + 1]);
                psum += w2s[2 * lane] * h0 + w2s[2 * lane + 1] * h1
                      + w2s[64 + 2 * lane] * h2 + w2s[64 + 2 * lane + 1] * h3;
            }
        }
        __syncwarp();
    }

#pragma unroll
    for (int off = 16; off; off >>= 1)
        psum += __shfl_xor_sync(0xffffffffu, psum, off);
    if (lane == 0) atomicAdd(&s_part, psum);
    __syncthreads();
    if (tid == 0) atomicAdd(&g_wsum[r], s_part);
}

// ---------------- kernel 5: beta = softmax(mean) --------------------------------------
__global__ void beta_kernel() {
    float w0 = g_wsum[0] / (float)NN;
    float w1 = g_wsum[1] / (float)NN;
    float w2 = g_wsum[2] / (float)NN;
    float m = fmaxf(w0, fmaxf(w1, w2));
    float e0 = expf(w0 - m), e1 = expf(w1 - m), e2 = expf(w2 - m);
    float s = e0 + e1 + e2;
    g_beta[0] = e0 / s; g_beta[1] = e1 / s; g_beta[2] = e2 / s;
}

// ---------------- kernel 6: fused output + leaky_relu ---------------------------------
__global__ void fuse_kernel(float* __restrict__ out) {
    int i = blockIdx.x * blockDim.x + threadIdx.x;
    if (i >= NN * DD / 4) return;
    float b0 = g_beta[0], b1 = g_beta[1], b2 = g_beta[2];
    float4 g = ((const float4*)g_geo)[i];
    float4 t = ((const float4*)g_trans)[i];
    float4 c = ((const float4*)g_cat)[i];
    float4 o;
    o.x = b0 * g.x + b1 * t.x + b2 * c.x;
    o.y = b0 * g.y + b1 * t.y + b2 * c.y;
    o.z = b0 * g.z + b1 * t.z + b2 * c.z;
    o.w = b0 * g.w + b1 * t.w + b2 * c.w;
    o.x = (o.x >= 0.f) ? o.x : 0.2f * o.x;
    o.y = (o.y >= 0.f) ? o.y : 0.2f * o.y;
    o.z = (o.z >= 0.f) ? o.z : 0.2f * o.z;
    o.w = (o.w >= 0.f) ? o.w : 0.2f * o.w;
    ((float4*)out)[i] = o;
}

// ---------------- launcher -------------------------------------------------------------
extern "C" void kernel_launch(void* const* d_in, const int* in_sizes, int n_in,
                              void* d_out, int out_size) {
    const float* feat = (const float*)d_in[0];
    const float* Wt   = (const float*)d_in[1];
    const float* w1   = (const float*)d_in[2];
    const float* b1   = (const float*)d_in[3];
    const float* w2   = (const float*)d_in[4];
    const float* tw   = (const float*)d_in[5];
    const int* gs = (const int*)d_in[6];
    const int* gd = (const int*)d_in[7];
    const int* cs = (const int*)d_in[8];
    const int* cd = (const int*)d_in[9];
    const int* ts = (const int*)d_in[10];
    const int* td = (const int*)d_in[11];
    float* out = (float*)d_out;

    const int SMEM_GEMM = 65536 + 32768;          // 98304
    const int SMEM_ATT  = 65536 + 32768 + 1024;   // 99328
    cudaFuncSetAttribute(gemm_f_kernel, cudaFuncAttributeMaxDynamicSharedMemorySize, SMEM_GEMM);
    cudaFuncSetAttribute(att_gemm_kernel, cudaFuncAttributeMaxDynamicSharedMemorySize, SMEM_ATT);

    zero_kernel<<<2048, 256>>>();
    gemm_f_kernel<<<296, 256, SMEM_GEMM>>>(feat, Wt);
    aggregate_kernel<<<(3 * NE) / 8, 256>>>(gs, gd, cs, cd, ts, td, tw);
    normalize_kernel<<<NN * DD / 4 / 256, 256>>>();
    att_gemm_kernel<<<dim3(25, 3, 4), 256, SMEM_ATT>>>(w1, b1, w2);
    beta_kernel<<<1, 1>>>();
    fuse_kernel<<<NN * DD / 4 / 256, 256>>>(out);
}

// round 3
// speedup vs baseline: 2.2788x; 2.2788x over previous
#include <cuda_runtime.h>
#include <cuda_bf16.h>
#include <cstdint>
#include <math.h>

#define NN 100000
#define NE 600000
#define DD 128
#define NTILES 782                 // ceil(100000/128)
#define TILES_TOTAL (3 * NTILES)

typedef unsigned long long u64;
typedef unsigned int u32;

// ---------------- device scratch ------------------------------------------------------
__device__ float g_f[NN * DD];
__device__ float g_geo[NN * DD];
__device__ float g_trans[NN * DD];
__device__ float g_cat[NN * DD];
__device__ float g_cnt_geo[NN];
__device__ float g_cnt_cat[NN];
__device__ float g_wsum[3];

// ---------------- small PTX helpers ---------------------------------------------------
__device__ __forceinline__ u64 pack2(float x) {
    u64 r; asm("mov.b64 %0, {%1, %1};" : "=l"(r) : "f"(x)); return r;
}
__device__ __forceinline__ void ffma2(u64& d, u64 a, u64 b) {
    asm("fma.rn.f32x2 %0, %1, %2, %0;" : "+l"(d) : "l"(a), "l"(b));
}
__device__ __forceinline__ float2 unpack2(u64 v) {
    float2 f; asm("mov.b64 {%0, %1}, %2;" : "=f"(f.x), "=f"(f.y) : "l"(v)); return f;
}
__device__ __forceinline__ float tanh_fast(float x) {
    float y; asm("tanh.approx.f32 %0, %1;" : "=f"(y) : "f"(x)); return y;
}
__device__ __forceinline__ u32 smem_u32(const void* p) {
    u32 a; asm("{ .reg .u64 t; cvta.to.shared.u64 t, %1; cvt.u32.u64 %0, t; }" : "=r"(a) : "l"(p));
    return a;
}
__device__ __forceinline__ void ldsm_x4(u32& r0, u32& r1, u32& r2, u32& r3, u32 addr) {
    asm volatile("ldmatrix.sync.aligned.m8n8.x4.shared.b16 {%0,%1,%2,%3}, [%4];"
                 : "=r"(r0), "=r"(r1), "=r"(r2), "=r"(r3) : "r"(addr));
}
__device__ __forceinline__ void ldsm_x2(u32& r0, u32& r1, u32 addr) {
    asm volatile("ldmatrix.sync.aligned.m8n8.x2.shared.b16 {%0,%1}, [%2];"
                 : "=r"(r0), "=r"(r1) : "r"(addr));
}
__device__ __forceinline__ void mma_16816(float* c, u32 a0, u32 a1, u32 a2, u32 a3,
                                          u32 b0, u32 b1) {
    asm volatile(
        "mma.sync.aligned.m16n8k16.row.col.f32.bf16.bf16.f32 "
        "{%0,%1,%2,%3}, {%4,%5,%6,%7}, {%8,%9}, {%0,%1,%2,%3};"
        : "+f"(c[0]), "+f"(c[1]), "+f"(c[2]), "+f"(c[3])
        : "r"(a0), "r"(a1), "r"(a2), "r"(a3), "r"(b0), "r"(b1));
}
__device__ __forceinline__ u64 pack_bf16x4(float x, float y, float z, float w) {
    __nv_bfloat162 p0 = __floats2bfloat162_rn(x, y);
    __nv_bfloat162 p1 = __floats2bfloat162_rn(z, w);
    return (u64)(*(u32*)&p0) | ((u64)(*(u32*)&p1) << 32);
}

// ---------------- f32x2 GEMM staging (for gemm_f) -------------------------------------
__device__ __forceinline__ void stage_w128(float* Ws, const float* __restrict__ Wsrc,
                                           int tid, int nthreads) {
    for (int idx = tid; idx < DD * DD; idx += nthreads) {
        int j = idx >> 7, k = idx & 127;
        int l, c;
        if (j < 64) { l = j >> 1; c = j & 1; }
        else        { l = (j - 64) >> 1; c = 2 + ((j - 64) & 1); }
        Ws[(k * 32 + l) * 4 + c] = Wsrc[idx];
    }
}

// ---------------- kernels: zero accumulators ------------------------------------------
__global__ void zero_big_kernel() {
    int i = blockIdx.x * blockDim.x + threadIdx.x;
    int stride = gridDim.x * blockDim.x;
    float4 z = make_float4(0.f, 0.f, 0.f, 0.f);
    const int n4 = NN * DD / 4;
    for (int k = i; k < n4; k += stride) {
        ((float4*)g_geo)[k] = z;
        ((float4*)g_cat)[k] = z;
        ((float4*)g_trans)[k] = z;
    }
}
__global__ void zero_small_kernel() {
    int i = blockIdx.x * blockDim.x + threadIdx.x;
    if (i < NN) { g_cnt_geo[i] = 0.f; g_cnt_cat[i] = 0.f; }
    if (i < 3) g_wsum[i] = 0.f;
}

// ---------------- kernel: f = feat @ W_tran^T (f32x2 FFMA, exact path) ----------------
__global__ __launch_bounds__(256) void gemm_f_kernel(const float* __restrict__ feat,
                                                     const float* __restrict__ W) {
    extern __shared__ char smem[];
    float* Ws = (float*)smem;                  // 65536 B
    u64* Zs = (u64*)(smem + 65536);            // 32768 B
    int tid = threadIdx.x;
    stage_w128(Ws, W, tid, 256);
    __syncthreads();

    const ulonglong2* Wv = (const ulonglong2*)Ws;
    int warp = tid >> 5, lane = tid & 31;
    u64* Zw = Zs + warp * 4 * DD;

    for (int base = blockIdx.x * 32 + warp * 4; base < NN; base += gridDim.x * 32) {
#pragma unroll
        for (int m = 0; m < 4; m++) {
            int n = base + m;
            float4 v = (n < NN) ? ((const float4*)feat)[n * 32 + lane]
                                : make_float4(0.f, 0.f, 0.f, 0.f);
            u64* zp = Zw + m * DD + lane * 4;
            zp[0] = pack2(v.x); zp[1] = pack2(v.y); zp[2] = pack2(v.z); zp[3] = pack2(v.w);
        }
        __syncwarp();

        u64 acc[4][2];
#pragma unroll
        for (int m = 0; m < 4; m++) { acc[m][0] = 0ull; acc[m][1] = 0ull; }

#pragma unroll 4
        for (int k = 0; k < DD; k++) {
            ulonglong2 wv = Wv[k * 32 + lane];
#pragma unroll
            for (int m = 0; m < 4; m++) {
                u64 zz = Zw[m * DD + k];
                ffma2(acc[m][0], zz, wv.x);
                ffma2(acc[m][1], zz, wv.y);
            }
        }

#pragma unroll
        for (int m = 0; m < 4; m++) {
            int n = base + m;
            if (n < NN) {
                float2 p0 = unpack2(acc[m][0]);
                float2 p1 = unpack2(acc[m][1]);
                ((float2*)g_f)[n * 64 + lane] = p0;
                ((float2*)g_f)[n * 64 + 32 + lane] = p1;
            }
        }
        __syncwarp();
    }
}

// ---------------- kernel: all three edge aggregations ---------------------------------
__global__ __launch_bounds__(256) void aggregate_kernel(
    const int* __restrict__ gs, const int* __restrict__ gd,
    const int* __restrict__ cs, const int* __restrict__ cd,
    const int* __restrict__ ts, const int* __restrict__ td,
    const float* __restrict__ tw) {
    long long gwid = (long long)blockIdx.x * (blockDim.x >> 5) + (threadIdx.x >> 5);
    int lane = threadIdx.x & 31;
    if (gwid >= 3LL * NE) return;
    int rel = (int)(gwid / NE);
    int e = (int)(gwid - (long long)rel * NE);

    int src, dst; float w = 1.f; float* base;
    if (rel == 0)      { src = gs[e]; dst = gd[e]; base = g_geo; }
    else if (rel == 1) { src = cs[e]; dst = cd[e]; base = g_cat; }
    else               { src = ts[e]; dst = td[e]; base = g_trans; w = tw[e]; }

    float4 v = ((const float4*)(g_f + (size_t)src * DD))[lane];
    if (rel == 2) { v.x *= w; v.y *= w; v.z *= w; v.w *= w; }

    float* p = base + (size_t)dst * DD + lane * 4;
    asm volatile("red.global.add.v4.f32 [%0], {%1,%2,%3,%4};"
                 :: "l"(p), "f"(v.x), "f"(v.y), "f"(v.z), "f"(v.w) : "memory");

    if (lane == 0) {
        if (rel == 0)      atomicAdd(&g_cnt_geo[dst], 1.0f);
        else if (rel == 1) atomicAdd(&g_cnt_cat[dst], 1.0f);
    }
}

// ---------------- kernel: attention via mma.sync bf16 HMMA ----------------------------
// Persistent. smem: B = W1 bf16 [512 x 128] padded to 136-elem rows (139264 B),
// A = z-tile bf16 [128 x 128] padded (34816 B), b1/w2 f32 (2048 B each).
// Warp w owns hidden slice [w*64, w*64+64). m-pair blocking: acc covers 32 rows x 64 cols.
#define ATT_LDA 136      // padded row stride in bf16 elements (272 B, conflict-free)
#define SM_B   0
#define SM_A   139264
#define SM_B1  174080
#define SM_W2  176128
#define SMEM_ATT 178176

__global__ __launch_bounds__(256) void att_mma_kernel(const float* __restrict__ W1,
                                                      const float* __restrict__ B1,
                                                      const float* __restrict__ W2) {
    extern __shared__ char smem[];
    u32 sb = smem_u32(smem);
    int tid = threadIdx.x, wid = tid >> 5, lane = tid & 31;

    // Stage B = W1 (f32 -> bf16), b1, w2
    for (int i = tid; i < 512 * 32; i += 256) {
        int j = i >> 5, q = i & 31;
        float4 v = ((const float4*)W1)[i];
        *(u64*)(smem + SM_B + (j * ATT_LDA + q * 4) * 2) = pack_bf16x4(v.x, v.y, v.z, v.w);
    }
    for (int i = tid; i < 512; i += 256) {
        ((float*)(smem + SM_B1))[i] = B1[i];
        ((float*)(smem + SM_W2))[i] = W2[i];
    }
    __syncthreads();

    const float* b1s = (const float*)(smem + SM_B1);
    const float* w2s = (const float*)(smem + SM_W2);

    float racc[3] = {0.f, 0.f, 0.f};

    for (int t = blockIdx.x; t < TILES_TOTAL; t += gridDim.x) {
        int rel = t / NTILES;
        int tile = t - rel * NTILES;
        int base = tile * 128;
        const float* zsrc = (rel == 0) ? g_geo : (rel == 1) ? g_trans : g_cat;
        const float* cnt = (rel == 0) ? g_cnt_geo : g_cnt_cat;

        // Stage A: 128 nodes x 128 feats, count-normalized for geo/cat, f32 -> bf16
        for (int i = tid; i < 128 * 32; i += 256) {
            int row = i >> 5, q = i & 31;
            int node = base + row;
            float4 v = make_float4(0.f, 0.f, 0.f, 0.f);
            float sc = 1.f;
            if (node < NN) {
                v = ((const float4*)zsrc)[(size_t)node * 32 + q];
                if (rel != 1) sc = 1.f / fmaxf(cnt[node], 1.f);
            }
            *(u64*)(smem + SM_A + (row * ATT_LDA + q * 4) * 2) =
                pack_bf16x4(v.x * sc, v.y * sc, v.z * sc, v.w * sc);
        }
        __syncthreads();

        float ps = 0.f;
#pragma unroll
        for (int mp = 0; mp < 4; mp++) {
            int m0 = mp * 32;
            float acc[2][8][4];
#pragma unroll
            for (int s = 0; s < 2; s++)
#pragma unroll
                for (int n = 0; n < 8; n++)
#pragma unroll
                    for (int e = 0; e < 4; e++) acc[s][n][e] = 0.f;

#pragma unroll
            for (int kk = 0; kk < 8; kk++) {
                // A fragments for rows [m0, m0+16) and [m0+16, m0+32)
                u32 a0[4], a1[4];
                u32 arow0 = m0 + (lane & 15);
                u32 acol = kk * 16 + ((lane >> 4) << 3);
                ldsm_x4(a0[0], a0[1], a0[2], a0[3],
                        sb + SM_A + (arow0 * ATT_LDA + acol) * 2);
                ldsm_x4(a1[0], a1[1], a1[2], a1[3],
                        sb + SM_A + ((arow0 + 16) * ATT_LDA + acol) * 2);

#pragma unroll
                for (int nn = 0; nn < 8; nn++) {
                    u32 b0, b1r;
                    u32 brow = (wid << 6) + nn * 8 + (lane & 7);
                    u32 bcol = kk * 16 + (((lane >> 3) & 1) << 3);
                    ldsm_x2(b0, b1r, sb + SM_B + (brow * ATT_LDA + bcol) * 2);
                    mma_16816(acc[0][nn], a0[0], a0[1], a0[2], a0[3], b0, b1r);
                    mma_16816(acc[1][nn], a1[0], a1[1], a1[2], a1[3], b0, b1r);
                }
            }

            // Epilogue: x = acc + b1; ps += w2 * tanh(x), masked on node validity
#pragma unroll
            for (int nn = 0; nn < 8; nn++) {
                int j0 = (wid << 6) + nn * 8 + ((lane & 3) << 1);
                float2 bb = *(const float2*)&b1s[j0];
                float2 ww = *(const float2*)&w2s[j0];
#pragma unroll
                for (int s = 0; s < 2; s++) {
                    int r0 = base + m0 + s * 16 + (lane >> 2);
                    const float* c = acc[s][nn];
                    if (r0 < NN)
                        ps += ww.x * tanh_fast(c[0] + bb.x) + ww.y * tanh_fast(c[1] + bb.y);
                    if (r0 + 8 < NN)
                        ps += ww.x * tanh_fast(c[2] + bb.x) + ww.y * tanh_fast(c[3] + bb.y);
                }
            }
        }
        racc[rel] += ps;
        __syncthreads();
    }

#pragma unroll
    for (int o = 16; o; o >>= 1) {
        racc[0] += __shfl_xor_sync(0xffffffffu, racc[0], o);
        racc[1] += __shfl_xor_sync(0xffffffffu, racc[1], o);
        racc[2] += __shfl_xor_sync(0xffffffffu, racc[2], o);
    }
    if (lane == 0) {
        atomicAdd(&g_wsum[0], racc[0]);
        atomicAdd(&g_wsum[1], racc[1]);
        atomicAdd(&g_wsum[2], racc[2]);
    }
}

// ---------------- kernel: fused output (inline softmax + normalization + leaky) -------
__global__ void fuse_kernel(float* __restrict__ out) {
    int i = blockIdx.x * blockDim.x + threadIdx.x;
    if (i >= NN * DD / 4) return;
    float w0 = g_wsum[0] * (1.f / NN);
    float w1 = g_wsum[1] * (1.f / NN);
    float w2 = g_wsum[2] * (1.f / NN);
    float m = fmaxf(w0, fmaxf(w1, w2));
    float e0 = expf(w0 - m), e1 = expf(w1 - m), e2 = expf(w2 - m);
    float inv = 1.f / (e0 + e1 + e2);
    float b0 = e0 * inv, b1 = e1 * inv, b2 = e2 * inv;

    int node = i >> 5;
    float ig = b0 / fmaxf(g_cnt_geo[node], 1.f);
    float ic = b2 / fmaxf(g_cnt_cat[node], 1.f);

    float4 g = ((const float4*)g_geo)[i];
    float4 t = ((const float4*)g_trans)[i];
    float4 c = ((const float4*)g_cat)[i];
    float4 o;
    o.x = ig * g.x + b1 * t.x + ic * c.x;
    o.y = ig * g.y + b1 * t.y + ic * c.y;
    o.z = ig * g.z + b1 * t.z + ic * c.z;
    o.w = ig * g.w + b1 * t.w + ic * c.w;
    o.x = (o.x >= 0.f) ? o.x : 0.2f * o.x;
    o.y = (o.y >= 0.f) ? o.y : 0.2f * o.y;
    o.z = (o.z >= 0.f) ? o.z : 0.2f * o.z;
    o.w = (o.w >= 0.f) ? o.w : 0.2f * o.w;
    ((float4*)out)[i] = o;
}

// ---------------- launcher -------------------------------------------------------------
extern "C" void kernel_launch(void* const* d_in, const int* in_sizes, int n_in,
                              void* d_out, int out_size) {
    const float* feat = (const float*)d_in[0];
    const float* Wt   = (const float*)d_in[1];
    const float* w1   = (const float*)d_in[2];
    const float* b1   = (const float*)d_in[3];
    const float* w2   = (const float*)d_in[4];
    const float* tw   = (const float*)d_in[5];
    const int* gs = (const int*)d_in[6];
    const int* gd = (const int*)d_in[7];
    const int* cs = (const int*)d_in[8];
    const int* cd = (const int*)d_in[9];
    const int* ts = (const int*)d_in[10];
    const int* td = (const int*)d_in[11];
    float* out = (float*)d_out;

    const int SMEM_GEMM = 65536 + 32768;
    cudaFuncSetAttribute(gemm_f_kernel, cudaFuncAttributeMaxDynamicSharedMemorySize, SMEM_GEMM);
    cudaFuncSetAttribute(att_mma_kernel, cudaFuncAttributeMaxDynamicSharedMemorySize, SMEM_ATT);

    zero_big_kernel<<<2048, 256>>>();
    zero_small_kernel<<<(NN + 255) / 256, 256>>>();
    gemm_f_kernel<<<296, 256, SMEM_GEMM>>>(feat, Wt);
    aggregate_kernel<<<(3 * NE) / 8, 256>>>(gs, gd, cs, cd, ts, td, tw);
    att_mma_kernel<<<148, 256, SMEM_ATT>>>(w1, b1, w2);
    fuse_kernel<<<NN * DD / 4 / 256, 256>>>(out);
}

// round 4
// speedup vs baseline: 3.2644x; 1.4325x over previous
#include <cuda_runtime.h>
#include <cuda_bf16.h>
#include <cstdint>
#include <math.h>

#define NN 100000
#define NE 600000
#define DD 128
#define CAP 64
#define NTILES 782                 // ceil(100000/128)
#define TILES_TOTAL (3 * NTILES)
#define OVF_MAX 4096

typedef unsigned long long u64;
typedef unsigned int u32;

// ---------------- device scratch ------------------------------------------------------
__device__ float g_agg[3 * NN * DD];          // f32 aggregates: [geo, trans, cat]
__device__ __nv_bfloat16 g_aggh[3 * NN * DD]; // bf16 copy for att staging
__device__ u32 g_deg[3 * NN];
__device__ int g_bucket[3 * NN * CAP];
__device__ float g_bw[NN * CAP];              // weights for trans buckets
__device__ float g_wcomb[512 * DD];           // W1 @ W_tran
__device__ float g_wsum[3];
__device__ u32 g_ovf_cnt;
__device__ int g_ovf[OVF_MAX * 4];            // rel, dst, src, w-bits

// ---------------- small PTX helpers ---------------------------------------------------
__device__ __forceinline__ u64 pack2(float x) {
    u64 r; asm("mov.b64 %0, {%1, %1};" : "=l"(r) : "f"(x)); return r;
}
__device__ __forceinline__ void ffma2(u64& d, u64 a, u64 b) {
    asm("fma.rn.f32x2 %0, %1, %2, %0;" : "+l"(d) : "l"(a), "l"(b));
}
__device__ __forceinline__ float2 unpack2(u64 v) {
    float2 f; asm("mov.b64 {%0, %1}, %2;" : "=f"(f.x), "=f"(f.y) : "l"(v)); return f;
}
__device__ __forceinline__ float tanh_fast(float x) {
    float y; asm("tanh.approx.f32 %0, %1;" : "=f"(y) : "f"(x)); return y;
}
__device__ __forceinline__ u32 smem_u32(const void* p) {
    u32 a; asm("{ .reg .u64 t; cvta.to.shared.u64 t, %1; cvt.u32.u64 %0, t; }" : "=r"(a) : "l"(p));
    return a;
}
__device__ __forceinline__ void ldsm_x4(u32& r0, u32& r1, u32& r2, u32& r3, u32 addr) {
    asm volatile("ldmatrix.sync.aligned.m8n8.x4.shared.b16 {%0,%1,%2,%3}, [%4];"
                 : "=r"(r0), "=r"(r1), "=r"(r2), "=r"(r3) : "r"(addr));
}
__device__ __forceinline__ void ldsm_x2(u32& r0, u32& r1, u32 addr) {
    asm volatile("ldmatrix.sync.aligned.m8n8.x2.shared.b16 {%0,%1}, [%2];"
                 : "=r"(r0), "=r"(r1) : "r"(addr));
}
__device__ __forceinline__ void mma_16816(float* c, u32 a0, u32 a1, u32 a2, u32 a3,
                                          u32 b0, u32 b1) {
    asm volatile(
        "mma.sync.aligned.m16n8k16.row.col.f32.bf16.bf16.f32 "
        "{%0,%1,%2,%3}, {%4,%5,%6,%7}, {%8,%9}, {%0,%1,%2,%3};"
        : "+f"(c[0]), "+f"(c[1]), "+f"(c[2]), "+f"(c[3])
        : "r"(a0), "r"(a1), "r"(a2), "r"(a3), "r"(b0), "r"(b1));
}
__device__ __forceinline__ u64 pack_bf16x4(float x, float y, float z, float w) {
    __nv_bfloat162 p0 = __floats2bfloat162_rn(x, y);
    __nv_bfloat162 p1 = __floats2bfloat162_rn(z, w);
    return (u64)(*(u32*)&p0) | ((u64)(*(u32*)&p1) << 32);
}

// ---------------- stage [128x128] f32 weights into paired-f32x2 smem layout -----------
__device__ __forceinline__ void stage_w128(float* Ws, const float* __restrict__ Wsrc,
                                           int tid, int nthreads) {
    for (int idx = tid; idx < DD * DD; idx += nthreads) {
        int j = idx >> 7, k = idx & 127;
        int l, c;
        if (j < 64) { l = j >> 1; c = j & 1; }
        else        { l = (j - 64) >> 1; c = 2 + ((j - 64) & 1); }
        Ws[(k * 32 + l) * 4 + c] = Wsrc[idx];
    }
}

// ---------------- kernel: zero counters ------------------------------------------------
__global__ void zero_kernel() {
    int i = blockIdx.x * blockDim.x + threadIdx.x;
    int stride = gridDim.x * blockDim.x;
    for (int k = i; k < 3 * NN; k += stride) g_deg[k] = 0u;
    if (i < 3) g_wsum[i] = 0.f;
    if (i == 3) g_ovf_cnt = 0u;
}

// ---------------- kernel: Wcomb = W1 @ W_tran ------------------------------------------
__global__ __launch_bounds__(256) void wcomb_kernel(const float* __restrict__ W1,
                                                    const float* __restrict__ Wt) {
    int idx = blockIdx.x * 256 + threadIdx.x;   // 65536 outputs
    int h = idx >> 7, j = idx & 127;
    float acc = 0.f;
#pragma unroll 8
    for (int k = 0; k < DD; k++)
        acc += W1[h * DD + k] * Wt[k * DD + j];
    g_wcomb[idx] = acc;
}

// ---------------- kernel: fill destination buckets -------------------------------------
__global__ __launch_bounds__(256) void fill_kernel(
    const int* __restrict__ gs, const int* __restrict__ gd,
    const int* __restrict__ cs, const int* __restrict__ cd,
    const int* __restrict__ ts, const int* __restrict__ td,
    const float* __restrict__ tw) {
    int i = blockIdx.x * blockDim.x + threadIdx.x;
    if (i >= 3 * NE) return;
    int rel = i / NE;
    int e = i - rel * NE;
    int src, dst; float w = 1.f;
    if (rel == 0)      { src = gs[e]; dst = gd[e]; }
    else if (rel == 1) { src = cs[e]; dst = cd[e]; }
    else               { src = ts[e]; dst = td[e]; w = tw[e]; }

    u32 pos = atomicAdd(&g_deg[rel * NN + dst], 1u);
    if (pos < CAP) {
        g_bucket[(rel * NN + dst) * CAP + pos] = src;
        if (rel == 2) g_bw[dst * CAP + pos] = w;
    } else {
        u32 o = atomicAdd(&g_ovf_cnt, 1u);
        if (o < OVF_MAX) {
            g_ovf[o * 4 + 0] = rel;
            g_ovf[o * 4 + 1] = dst;
            g_ovf[o * 4 + 2] = src;
            g_ovf[o * 4 + 3] = __float_as_int(w);
        }
    }
}

// ---------------- kernel: per-destination gather-sum (one warp per (rel,dst)) ---------
__global__ __launch_bounds__(256) void gather_kernel(const float* __restrict__ feat) {
    int gw = blockIdx.x * (blockDim.x >> 5) + (threadIdx.x >> 5);
    int lane = threadIdx.x & 31;
    if (gw >= 3 * NN) return;
    int rel = gw / NN, dst = gw - rel * NN;

    u32 d = g_deg[rel * NN + dst];
    u32 lim = d < CAP ? d : CAP;
    const int* bk = &g_bucket[(size_t)(rel * NN + dst) * CAP];

    int s0 = (lane < (int)lim) ? bk[lane] : 0;
    int s1 = (32 + lane < (int)lim) ? bk[32 + lane] : 0;
    float w0 = 1.f, w1 = 1.f;
    if (rel == 2) {
        const float* bw = &g_bw[(size_t)dst * CAP];
        w0 = (lane < (int)lim) ? bw[lane] : 0.f;
        w1 = (32 + lane < (int)lim) ? bw[32 + lane] : 0.f;
    }

    float4 acc = make_float4(0.f, 0.f, 0.f, 0.f);
    const float4* f4 = (const float4*)feat;
    u32 e = 0;
    for (; e + 2 <= lim; e += 2) {
        int sa = __shfl_sync(0xffffffffu, (e < 32) ? s0 : s1, e & 31);
        int sb = __shfl_sync(0xffffffffu, (e + 1 < 32) ? s0 : s1, (e + 1) & 31);
        float wa = __shfl_sync(0xffffffffu, (e < 32) ? w0 : w1, e & 31);
        float wb = __shfl_sync(0xffffffffu, (e + 1 < 32) ? w0 : w1, (e + 1) & 31);
        float4 va = f4[(size_t)sa * 32 + lane];
        float4 vb = f4[(size_t)sb * 32 + lane];
        acc.x += va.x * wa + vb.x * wb;
        acc.y += va.y * wa + vb.y * wb;
        acc.z += va.z * wa + vb.z * wb;
        acc.w += va.w * wa + vb.w * wb;
    }
    if (e < lim) {
        int sa = __shfl_sync(0xffffffffu, (e < 32) ? s0 : s1, e & 31);
        float wa = __shfl_sync(0xffffffffu, (e < 32) ? w0 : w1, e & 31);
        float4 va = f4[(size_t)sa * 32 + lane];
        acc.x += va.x * wa; acc.y += va.y * wa; acc.z += va.z * wa; acc.w += va.w * wa;
    }

    float sc = (rel == 2) ? 1.f : 1.f / fmaxf((float)d, 1.f);
    acc.x *= sc; acc.y *= sc; acc.z *= sc; acc.w *= sc;

    size_t row = (size_t)(rel * NN + dst);
    ((float4*)g_agg)[row * 32 + lane] = acc;
    ((u64*)g_aggh)[row * 32 + lane] = pack_bf16x4(acc.x, acc.y, acc.z, acc.w);
}

// ---------------- kernel: exact fixup for bucket overflow (expected count: 0) ----------
__global__ void fixup_kernel(const float* __restrict__ feat) {
    u32 cnt = g_ovf_cnt;
    if (cnt > OVF_MAX) cnt = OVF_MAX;
    int warp = threadIdx.x >> 5, lane = threadIdx.x & 31;
    for (u32 o = warp; o < cnt; o += 8) {
        int rel = g_ovf[o * 4 + 0];
        int dst = g_ovf[o * 4 + 1];
        int src = g_ovf[o * 4 + 2];
        float w = __int_as_float(g_ovf[o * 4 + 3]);
        float sc = (rel == 2) ? w : 1.f / fmaxf((float)g_deg[rel * NN + dst], 1.f);
        float4 v = ((const float4*)feat)[(size_t)src * 32 + lane];
        float* p = g_agg + ((size_t)(rel * NN + dst)) * DD + lane * 4;
        asm volatile("red.global.add.v4.f32 [%0], {%1,%2,%3,%4};"
                     :: "l"(p), "f"(v.x * sc), "f"(v.y * sc), "f"(v.z * sc), "f"(v.w * sc)
                     : "memory");
    }
}

// ---------------- kernel: attention via mma.sync bf16 HMMA -----------------------------
// B = Wcomb bf16 [512 x 128] padded rows; A = agg tile bf16 [128 x 128] padded.
#define ATT_LDA 136      // padded row stride (bf16 elems); 272 B
#define SM_B   0
#define SM_A   139264
#define SM_B1  174080
#define SM_W2  176128
#define SMEM_ATT 178176

__global__ __launch_bounds__(256) void att_mma_kernel(const float* __restrict__ B1,
                                                      const float* __restrict__ W2) {
    extern __shared__ char smem[];
    u32 sb = smem_u32(smem);
    int tid = threadIdx.x, wid = tid >> 5, lane = tid & 31;

    // Stage B = Wcomb (f32 -> bf16), b1, w2
    for (int i = tid; i < 512 * 32; i += 256) {
        int j = i >> 5, q = i & 31;
        float4 v = ((const float4*)g_wcomb)[i];
        *(u64*)(smem + SM_B + (j * ATT_LDA + q * 4) * 2) = pack_bf16x4(v.x, v.y, v.z, v.w);
    }
    for (int i = tid; i < 512; i += 256) {
        ((float*)(smem + SM_B1))[i] = B1[i];
        ((float*)(smem + SM_W2))[i] = W2[i];
    }
    __syncthreads();

    const float* b1s = (const float*)(smem + SM_B1);
    const float* w2s = (const float*)(smem + SM_W2);

    float racc[3] = {0.f, 0.f, 0.f};

    for (int t = blockIdx.x; t < TILES_TOTAL; t += gridDim.x) {
        int rel = t / NTILES;
        int tile = t - rel * NTILES;
        int base = tile * 128;

        // Stage A: 128 node rows of precomputed bf16 aggregates
        for (int i = tid; i < 128 * 16; i += 256) {
            int row = i >> 4, q = i & 15;
            int node = base + row;
            uint4 v = make_uint4(0u, 0u, 0u, 0u);
            if (node < NN)
                v = ((const uint4*)g_aggh)[(size_t)(rel * NN + node) * 16 + q];
            *(uint4*)(smem + SM_A + row * (ATT_LDA * 2) + q * 16) = v;
        }
        __syncthreads();

        float ps = 0.f;
#pragma unroll
        for (int mp = 0; mp < 4; mp++) {
            int m0 = mp * 32;
            float acc[2][8][4];
#pragma unroll
            for (int s = 0; s < 2; s++)
#pragma unroll
                for (int n = 0; n < 8; n++)
#pragma unroll
                    for (int ee = 0; ee < 4; ee++) acc[s][n][ee] = 0.f;

#pragma unroll
            for (int kk = 0; kk < 8; kk++) {
                u32 a0[4], a1[4];
                u32 arow0 = m0 + (lane & 15);
                u32 acol = kk * 16 + ((lane >> 4) << 3);
                ldsm_x4(a0[0], a0[1], a0[2], a0[3],
                        sb + SM_A + (arow0 * ATT_LDA + acol) * 2);
                ldsm_x4(a1[0], a1[1], a1[2], a1[3],
                        sb + SM_A + ((arow0 + 16) * ATT_LDA + acol) * 2);

#pragma unroll
                for (int nn = 0; nn < 8; nn++) {
                    u32 b0, b1r;
                    u32 brow = (wid << 6) + nn * 8 + (lane & 7);
                    u32 bcol = kk * 16 + (((lane >> 3) & 1) << 3);
                    ldsm_x2(b0, b1r, sb + SM_B + (brow * ATT_LDA + bcol) * 2);
                    mma_16816(acc[0][nn], a0[0], a0[1], a0[2], a0[3], b0, b1r);
                    mma_16816(acc[1][nn], a1[0], a1[1], a1[2], a1[3], b0, b1r);
                }
            }

#pragma unroll
            for (int nn = 0; nn < 8; nn++) {
                int j0 = (wid << 6) + nn * 8 + ((lane & 3) << 1);
                float2 bb = *(const float2*)&b1s[j0];
                float2 ww = *(const float2*)&w2s[j0];
#pragma unroll
                for (int s = 0; s < 2; s++) {
                    int r0 = base + m0 + s * 16 + (lane >> 2);
                    const float* c = acc[s][nn];
                    if (r0 < NN)
                        ps += ww.x * tanh_fast(c[0] + bb.x) + ww.y * tanh_fast(c[1] + bb.y);
                    if (r0 + 8 < NN)
                        ps += ww.x * tanh_fast(c[2] + bb.x) + ww.y * tanh_fast(c[3] + bb.y);
                }
            }
        }
        racc[rel] += ps;
        __syncthreads();
    }

#pragma unroll
    for (int o = 16; o; o >>= 1) {
        racc[0] += __shfl_xor_sync(0xffffffffu, racc[0], o);
        racc[1] += __shfl_xor_sync(0xffffffffu, racc[1], o);
        racc[2] += __shfl_xor_sync(0xffffffffu, racc[2], o);
    }
    if (lane == 0) {
        atomicAdd(&g_wsum[0], racc[0]);
        atomicAdd(&g_wsum[1], racc[1]);
        atomicAdd(&g_wsum[2], racc[2]);
    }
}

// ---------------- kernel: fuse = leaky((b0*geo + b1*trans + b2*cat) @ Wt^T) ------------
__global__ __launch_bounds__(256) void fuse_kernel(const float* __restrict__ Wt,
                                                   float* __restrict__ out) {
    extern __shared__ char smem[];
    float* Ws = (float*)smem;                  // 65536 B
    u64* Zs = (u64*)(smem + 65536);            // 32768 B
    int tid = threadIdx.x;
    stage_w128(Ws, Wt, tid, 256);
    __syncthreads();

    float w0 = g_wsum[0] * (1.f / NN);
    float w1 = g_wsum[1] * (1.f / NN);
    float w2 = g_wsum[2] * (1.f / NN);
    float m = fmaxf(w0, fmaxf(w1, w2));
    float e0 = expf(w0 - m), e1 = expf(w1 - m), e2 = expf(w2 - m);
    float inv = 1.f / (e0 + e1 + e2);
    float b0 = e0 * inv, b1 = e1 * inv, b2 = e2 * inv;

    const ulonglong2* Wv = (const ulonglong2*)Ws;
    int warp = tid >> 5, lane = tid & 31;
    u64* Zw = Zs + warp * 4 * DD;
    const float4* geo4 = (const float4*)g_agg;
    const float4* trn4 = geo4 + (size_t)NN * 32;
    const float4* cat4 = trn4 + (size_t)NN * 32;

    for (int base = blockIdx.x * 32 + warp * 4; base < NN; base += gridDim.x * 32) {
#pragma unroll
        for (int mm = 0; mm < 4; mm++) {
            int n = base + mm;
            float4 v = make_float4(0.f, 0.f, 0.f, 0.f);
            if (n < NN) {
                float4 g = geo4[(size_t)n * 32 + lane];
                float4 t = trn4[(size_t)n * 32 + lane];
                float4 c = cat4[(size_t)n * 32 + lane];
                v.x = b0 * g.x + b1 * t.x + b2 * c.x;
                v.y = b0 * g.y + b1 * t.y + b2 * c.y;
                v.z = b0 * g.z + b1 * t.z + b2 * c.z;
                v.w = b0 * g.w + b1 * t.w + b2 * c.w;
            }
            u64* zp = Zw + mm * DD + lane * 4;
            zp[0] = pack2(v.x); zp[1] = pack2(v.y); zp[2] = pack2(v.z); zp[3] = pack2(v.w);
        }
        __syncwarp();

        u64 acc[4][2];
#pragma unroll
        for (int mm = 0; mm < 4; mm++) { acc[mm][0] = 0ull; acc[mm][1] = 0ull; }

#pragma unroll 4
        for (int k = 0; k < DD; k++) {
            ulonglong2 wv = Wv[k * 32 + lane];
#pragma unroll
            for (int mm = 0; mm < 4; mm++) {
                u64 zz = Zw[mm * DD + k];
                ffma2(acc[mm][0], zz, wv.x);
                ffma2(acc[mm][1], zz, wv.y);
            }
        }

#pragma unroll
        for (int mm = 0; mm < 4; mm++) {
            int n = base + mm;
            if (n < NN) {
                float2 p0 = unpack2(acc[mm][0]);
                float2 p1 = unpack2(acc[mm][1]);
                p0.x = (p0.x >= 0.f) ? p0.x : 0.2f * p0.x;
                p0.y = (p0.y >= 0.f) ? p0.y : 0.2f * p0.y;
                p1.x = (p1.x >= 0.f) ? p1.x : 0.2f * p1.x;
                p1.y = (p1.y >= 0.f) ? p1.y : 0.2f * p1.y;
                ((float2*)out)[n * 64 + lane] = p0;
                ((float2*)out)[n * 64 + 32 + lane] = p1;
            }
        }
        __syncwarp();
    }
}

// ---------------- launcher -------------------------------------------------------------
extern "C" void kernel_launch(void* const* d_in, const int* in_sizes, int n_in,
                              void* d_out, int out_size) {
    const float* feat = (const float*)d_in[0];
    const float* Wt   = (const float*)d_in[1];
    const float* w1   = (const float*)d_in[2];
    const float* b1   = (const float*)d_in[3];
    const float* w2   = (const float*)d_in[4];
    const float* tw   = (const float*)d_in[5];
    const int* gs = (const int*)d_in[6];
    const int* gd = (const int*)d_in[7];
    const int* cs = (const int*)d_in[8];
    const int* cd = (const int*)d_in[9];
    const int* ts = (const int*)d_in[10];
    const int* td = (const int*)d_in[11];
    float* out = (float*)d_out;

    const int SMEM_FUSE = 65536 + 32768;
    cudaFuncSetAttribute(att_mma_kernel, cudaFuncAttributeMaxDynamicSharedMemorySize, SMEM_ATT);
    cudaFuncSetAttribute(fuse_kernel, cudaFuncAttributeMaxDynamicSharedMemorySize, SMEM_FUSE);

    zero_kernel<<<(3 * NN + 255) / 256, 256>>>();
    wcomb_kernel<<<256, 256>>>(w1, Wt);
    fill_kernel<<<(3 * NE + 255) / 256, 256>>>(gs, gd, cs, cd, ts, td, tw);
    gather_kernel<<<(3 * NN + 7) / 8, 256>>>(feat);
    fixup_kernel<<<1, 256>>>(feat);
    att_mma_kernel<<<148, 256, SMEM_ATT>>>(b1, w2);
    fuse_kernel<<<296, 256, SMEM_FUSE>>>(Wt, out);
}

// round 5
// speedup vs baseline: 3.4018x; 1.0421x over previous
#include <cuda_runtime.h>
#include <cuda_bf16.h>
#include <cuda_fp16.h>
#include <cstdint>
#include <math.h>

#define NN 100000
#define NE 600000
#define DD 128
#define CAP 64
#define NTILES 782                 // ceil(100000/128)
#define TILES_TOTAL (3 * NTILES)
#define OVF_MAX 4096

typedef unsigned long long u64;
typedef unsigned int u32;

// ---------------- device scratch ------------------------------------------------------
__device__ float g_agg[3 * NN * DD];          // f32 aggregates: [geo, trans, cat]
__device__ __nv_bfloat16 g_aggh[3 * NN * DD]; // bf16 copy for att staging
__device__ u32 g_deg[3 * NN];
__device__ int g_bucket[3 * NN * CAP];
__device__ float g_bw[NN * CAP];              // weights for trans buckets
__device__ float g_wcomb[512 * DD];           // W1 @ W_tran
__device__ float g_wsum[3];
__device__ u32 g_ovf_cnt;
__device__ int g_ovf[OVF_MAX * 4];            // rel, dst, src, w-bits

// ---------------- small PTX helpers ---------------------------------------------------
__device__ __forceinline__ u64 pack2(float x) {
    u64 r; asm("mov.b64 %0, {%1, %1};" : "=l"(r) : "f"(x)); return r;
}
__device__ __forceinline__ void ffma2(u64& d, u64 a, u64 b) {
    asm("fma.rn.f32x2 %0, %1, %2, %0;" : "+l"(d) : "l"(a), "l"(b));
}
__device__ __forceinline__ float2 unpack2(u64 v) {
    float2 f; asm("mov.b64 {%0, %1}, %2;" : "=f"(f.x), "=f"(f.y) : "l"(v)); return f;
}
__device__ __forceinline__ __half2 tanh2(__half2 x) {
    u32 xi = *(u32*)&x, yi;
    asm("tanh.approx.f16x2 %0, %1;" : "=r"(yi) : "r"(xi));
    return *(__half2*)&yi;
}
__device__ __forceinline__ u32 smem_u32(const void* p) {
    u32 a; asm("{ .reg .u64 t; cvta.to.shared.u64 t, %1; cvt.u32.u64 %0, t; }" : "=r"(a) : "l"(p));
    return a;
}
__device__ __forceinline__ void ldsm_x4(u32& r0, u32& r1, u32& r2, u32& r3, u32 addr) {
    asm volatile("ldmatrix.sync.aligned.m8n8.x4.shared.b16 {%0,%1,%2,%3}, [%4];"
                 : "=r"(r0), "=r"(r1), "=r"(r2), "=r"(r3) : "r"(addr));
}
__device__ __forceinline__ void ldsm_x2(u32& r0, u32& r1, u32 addr) {
    asm volatile("ldmatrix.sync.aligned.m8n8.x2.shared.b16 {%0,%1}, [%2];"
                 : "=r"(r0), "=r"(r1) : "r"(addr));
}
__device__ __forceinline__ void mma_16816(float* c, u32 a0, u32 a1, u32 a2, u32 a3,
                                          u32 b0, u32 b1) {
    asm volatile(
        "mma.sync.aligned.m16n8k16.row.col.f32.bf16.bf16.f32 "
        "{%0,%1,%2,%3}, {%4,%5,%6,%7}, {%8,%9}, {%0,%1,%2,%3};"
        : "+f"(c[0]), "+f"(c[1]), "+f"(c[2]), "+f"(c[3])
        : "r"(a0), "r"(a1), "r"(a2), "r"(a3), "r"(b0), "r"(b1));
}
__device__ __forceinline__ u64 pack_bf16x4(float x, float y, float z, float w) {
    __nv_bfloat162 p0 = __floats2bfloat162_rn(x, y);
    __nv_bfloat162 p1 = __floats2bfloat162_rn(z, w);
    return (u64)(*(u32*)&p0) | ((u64)(*(u32*)&p1) << 32);
}

// ---------------- stage [128x128] f32 weights into paired-f32x2 smem layout -----------
__device__ __forceinline__ void stage_w128(float* Ws, const float* __restrict__ Wsrc,
                                           int tid, int nthreads) {
    for (int idx = tid; idx < DD * DD; idx += nthreads) {
        int j = idx >> 7, k = idx & 127;
        int l, c;
        if (j < 64) { l = j >> 1; c = j & 1; }
        else        { l = (j - 64) >> 1; c = 2 + ((j - 64) & 1); }
        Ws[(k * 32 + l) * 4 + c] = Wsrc[idx];
    }
}

// ---------------- kernel: zero counters ------------------------------------------------
__global__ void zero_kernel() {
    int i = blockIdx.x * blockDim.x + threadIdx.x;
    int stride = gridDim.x * blockDim.x;
    for (int k = i; k < 3 * NN; k += stride) g_deg[k] = 0u;
    if (i < 3) g_wsum[i] = 0.f;
    if (i == 3) g_ovf_cnt = 0u;
}

// ---------------- kernel: Wcomb = W1 @ W_tran ------------------------------------------
__global__ __launch_bounds__(256) void wcomb_kernel(const float* __restrict__ W1,
                                                    const float* __restrict__ Wt) {
    int idx = blockIdx.x * 256 + threadIdx.x;   // 65536 outputs
    int h = idx >> 7, j = idx & 127;
    float acc = 0.f;
#pragma unroll 8
    for (int k = 0; k < DD; k++)
        acc += W1[h * DD + k] * Wt[k * DD + j];
    g_wcomb[idx] = acc;
}

// ---------------- kernel: fill destination buckets -------------------------------------
__global__ __launch_bounds__(256) void fill_kernel(
    const int* __restrict__ gs, const int* __restrict__ gd,
    const int* __restrict__ cs, const int* __restrict__ cd,
    const int* __restrict__ ts, const int* __restrict__ td,
    const float* __restrict__ tw) {
    int i = blockIdx.x * blockDim.x + threadIdx.x;
    if (i >= 3 * NE) return;
    int rel = i / NE;
    int e = i - rel * NE;
    int src, dst; float w = 1.f;
    if (rel == 0)      { src = gs[e]; dst = gd[e]; }
    else if (rel == 1) { src = cs[e]; dst = cd[e]; }
    else               { src = ts[e]; dst = td[e]; w = tw[e]; }

    u32 pos = atomicAdd(&g_deg[rel * NN + dst], 1u);
    if (pos < CAP) {
        g_bucket[(rel * NN + dst) * CAP + pos] = src;
        if (rel == 2) g_bw[dst * CAP + pos] = w;
    } else {
        u32 o = atomicAdd(&g_ovf_cnt, 1u);
        if (o < OVF_MAX) {
            g_ovf[o * 4 + 0] = rel;
            g_ovf[o * 4 + 1] = dst;
            g_ovf[o * 4 + 2] = src;
            g_ovf[o * 4 + 3] = __float_as_int(w);
        }
    }
}

// ---------------- kernel: per-destination gather-sum (persistent, MLP=8) --------------
__global__ __launch_bounds__(256) void gather_kernel(const float* __restrict__ feat) {
    int warps_total = gridDim.x * (blockDim.x >> 5);
    int gw0 = blockIdx.x * (blockDim.x >> 5) + (threadIdx.x >> 5);
    int lane = threadIdx.x & 31;
    const float4* f4 = (const float4*)feat;

    for (int gw = gw0; gw < 3 * NN; gw += warps_total) {
        int rel = gw / NN, dst = gw - rel * NN;

        u32 d = g_deg[rel * NN + dst];
        u32 lim = d < CAP ? d : CAP;
        const int* bk = &g_bucket[(size_t)(rel * NN + dst) * CAP];

        int s0 = (lane < (int)lim) ? bk[lane] : 0;
        int s1 = (32 + lane < (int)lim) ? bk[32 + lane] : 0;
        float w0 = 1.f, w1 = 1.f;
        if (rel == 2) {
            const float* bw = &g_bw[(size_t)dst * CAP];
            w0 = (lane < (int)lim) ? bw[lane] : 0.f;
            w1 = (32 + lane < (int)lim) ? bw[32 + lane] : 0.f;
        }

        float4 acc = make_float4(0.f, 0.f, 0.f, 0.f);
        for (u32 e = 0; e < lim; e += 8) {
            float4 v[8]; float wv[8];
#pragma unroll
            for (int j = 0; j < 8; j++) {
                u32 idx = e + j;
                int sj = __shfl_sync(0xffffffffu, (idx < 32) ? s0 : s1, idx & 31);
                float wj = __shfl_sync(0xffffffffu, (idx < 32) ? w0 : w1, idx & 31);
                bool p = idx < lim;
                // sj is 0 when the owning lane was out-of-range -> address always valid
                v[j] = p ? f4[(size_t)sj * 32 + lane] : make_float4(0.f, 0.f, 0.f, 0.f);
                wv[j] = p ? wj : 0.f;
            }
#pragma unroll
            for (int j = 0; j < 8; j++) {
                acc.x += v[j].x * wv[j];
                acc.y += v[j].y * wv[j];
                acc.z += v[j].z * wv[j];
                acc.w += v[j].w * wv[j];
            }
        }

        float sc = (rel == 2) ? 1.f : 1.f / fmaxf((float)d, 1.f);
        acc.x *= sc; acc.y *= sc; acc.z *= sc; acc.w *= sc;

        size_t row = (size_t)(rel * NN + dst);
        ((float4*)g_agg)[row * 32 + lane] = acc;
        ((u64*)g_aggh)[row * 32 + lane] = pack_bf16x4(acc.x, acc.y, acc.z, acc.w);
    }
}

// ---------------- kernel: exact fixup for bucket overflow (expected count: 0) ----------
__global__ void fixup_kernel(const float* __restrict__ feat) {
    u32 cnt = g_ovf_cnt;
    if (cnt > OVF_MAX) cnt = OVF_MAX;
    int warp = threadIdx.x >> 5, lane = threadIdx.x & 31;
    for (u32 o = warp; o < cnt; o += 8) {
        int rel = g_ovf[o * 4 + 0];
        int dst = g_ovf[o * 4 + 1];
        int src = g_ovf[o * 4 + 2];
        float w = __int_as_float(g_ovf[o * 4 + 3]);
        float sc = (rel == 2) ? w : 1.f / fmaxf((float)g_deg[rel * NN + dst], 1.f);
        float4 v = ((const float4*)feat)[(size_t)src * 32 + lane];
        float* p = g_agg + ((size_t)(rel * NN + dst)) * DD + lane * 4;
        asm volatile("red.global.add.v4.f32 [%0], {%1,%2,%3,%4};"
                     :: "l"(p), "f"(v.x * sc), "f"(v.y * sc), "f"(v.z * sc), "f"(v.w * sc)
                     : "memory");
    }
}

// ---------------- kernel: attention via mma.sync bf16 HMMA -----------------------------
#define ATT_LDA 136      // padded row stride (bf16 elems); 272 B
#define SM_B   0
#define SM_A   139264
#define SM_B1  174080
#define SM_W2  176128
#define SMEM_ATT 178176

__global__ __launch_bounds__(256) void att_mma_kernel(const float* __restrict__ B1,
                                                      const float* __restrict__ W2) {
    extern __shared__ char smem[];
    u32 sb = smem_u32(smem);
    int tid = threadIdx.x, wid = tid >> 5, lane = tid & 31;

    // Stage B = Wcomb (f32 -> bf16), b1, w2
    for (int i = tid; i < 512 * 32; i += 256) {
        int j = i >> 5, q = i & 31;
        float4 v = ((const float4*)g_wcomb)[i];
        *(u64*)(smem + SM_B + (j * ATT_LDA + q * 4) * 2) = pack_bf16x4(v.x, v.y, v.z, v.w);
    }
    for (int i = tid; i < 512; i += 256) {
        ((float*)(smem + SM_B1))[i] = B1[i];
        ((float*)(smem + SM_W2))[i] = W2[i];
    }
    __syncthreads();

    const float* b1s = (const float*)(smem + SM_B1);
    const float* w2s = (const float*)(smem + SM_W2);

    // Per-thread tile-invariant half2 bias/weight pairs for the epilogue
    __half2 bh[8], wh[8];
#pragma unroll
    for (int nn = 0; nn < 8; nn++) {
        int j0 = (wid << 6) + nn * 8 + ((lane & 3) << 1);
        bh[nn] = __floats2half2_rn(b1s[j0], b1s[j0 + 1]);
        wh[nn] = __floats2half2_rn(w2s[j0], w2s[j0 + 1]);
    }

    float racc[3] = {0.f, 0.f, 0.f};

    for (int t = blockIdx.x; t < TILES_TOTAL; t += gridDim.x) {
        int rel = t / NTILES;
        int tile = t - rel * NTILES;
        int base = tile * 128;

        // Stage A: 128 node rows of precomputed bf16 aggregates
        for (int i = tid; i < 128 * 16; i += 256) {
            int row = i >> 4, q = i & 15;
            int node = base + row;
            uint4 v = make_uint4(0u, 0u, 0u, 0u);
            if (node < NN)
                v = ((const uint4*)g_aggh)[(size_t)(rel * NN + node) * 16 + q];
            *(uint4*)(smem + SM_A + row * (ATT_LDA * 2) + q * 16) = v;
        }
        __syncthreads();

        float ps = 0.f;
#pragma unroll
        for (int mp = 0; mp < 4; mp++) {
            int m0 = mp * 32;
            float acc[2][8][4];
#pragma unroll
            for (int s = 0; s < 2; s++)
#pragma unroll
                for (int n = 0; n < 8; n++)
#pragma unroll
                    for (int ee = 0; ee < 4; ee++) acc[s][n][ee] = 0.f;

#pragma unroll
            for (int kk = 0; kk < 8; kk++) {
                u32 a0[4], a1[4];
                u32 arow0 = m0 + (lane & 15);
                u32 acol = kk * 16 + ((lane >> 4) << 3);
                ldsm_x4(a0[0], a0[1], a0[2], a0[3],
                        sb + SM_A + (arow0 * ATT_LDA + acol) * 2);
                ldsm_x4(a1[0], a1[1], a1[2], a1[3],
                        sb + SM_A + ((arow0 + 16) * ATT_LDA + acol) * 2);

#pragma unroll
                for (int nn = 0; nn < 8; nn++) {
                    u32 b0, b1r;
                    u32 brow = (wid << 6) + nn * 8 + (lane & 7);
                    u32 bcol = kk * 16 + (((lane >> 3) & 1) << 3);
                    ldsm_x2(b0, b1r, sb + SM_B + (brow * ATT_LDA + bcol) * 2);
                    mma_16816(acc[0][nn], a0[0], a0[1], a0[2], a0[3], b0, b1r);
                    mma_16816(acc[1][nn], a1[0], a1[1], a1[2], a1[3], b0, b1r);
                }
            }

            // Epilogue (f16x2): hsum += wh * tanh(acc + bh), masked on node validity
            __half2 hsum = __floats2half2_rn(0.f, 0.f);
            bool v0 = (base + m0 + (lane >> 2)) < NN;
            bool v1 = (base + m0 + 8 + (lane >> 2)) < NN;
            bool v2 = (base + m0 + 16 + (lane >> 2)) < NN;
            bool v3 = (base + m0 + 24 + (lane >> 2)) < NN;
#pragma unroll
            for (int nn = 0; nn < 8; nn++) {
#pragma unroll
                for (int s = 0; s < 2; s++) {
                    const float* c = acc[s][nn];
                    bool pa = s ? v2 : v0;
                    bool pb = s ? v3 : v1;
                    if (pa) {
                        __half2 x = __hadd2(__floats2half2_rn(c[0], c[1]), bh[nn]);
                        hsum = __hfma2(tanh2(x), wh[nn], hsum);
                    }
                    if (pb) {
                        __half2 x = __hadd2(__floats2half2_rn(c[2], c[3]), bh[nn]);
                        hsum = __hfma2(tanh2(x), wh[nn], hsum);
                    }
                }
            }
            float2 hs = __half22float2(hsum);
            ps += hs.x + hs.y;
        }
        racc[rel] += ps;
        __syncthreads();
    }

#pragma unroll
    for (int o = 16; o; o >>= 1) {
        racc[0] += __shfl_xor_sync(0xffffffffu, racc[0], o);
        racc[1] += __shfl_xor_sync(0xffffffffu, racc[1], o);
        racc[2] += __shfl_xor_sync(0xffffffffu, racc[2], o);
    }
    if (lane == 0) {
        atomicAdd(&g_wsum[0], racc[0]);
        atomicAdd(&g_wsum[1], racc[1]);
        atomicAdd(&g_wsum[2], racc[2]);
    }
}

// ---------------- kernel: fuse = leaky((b0*geo + b1*trans + b2*cat) @ Wt^T) ------------
__global__ __launch_bounds__(256) void fuse_kernel(const float* __restrict__ Wt,
                                                   float* __restrict__ out) {
    extern __shared__ char smem[];
    float* Ws = (float*)smem;                  // 65536 B
    u64* Zs = (u64*)(smem + 65536);            // 32768 B
    int tid = threadIdx.x;
    stage_w128(Ws, Wt, tid, 256);
    __syncthreads();

    float w0 = g_wsum[0] * (1.f / NN);
    float w1 = g_wsum[1] * (1.f / NN);
    float w2 = g_wsum[2] * (1.f / NN);
    float m = fmaxf(w0, fmaxf(w1, w2));
    float e0 = expf(w0 - m), e1 = expf(w1 - m), e2 = expf(w2 - m);
    float inv = 1.f / (e0 + e1 + e2);
    float b0 = e0 * inv, b1 = e1 * inv, b2 = e2 * inv;

    const ulonglong2* Wv = (const ulonglong2*)Ws;
    int warp = tid >> 5, lane = tid & 31;
    u64* Zw = Zs + warp * 4 * DD;
    const float4* geo4 = (const float4*)g_agg;
    const float4* trn4 = geo4 + (size_t)NN * 32;
    const float4* cat4 = trn4 + (size_t)NN * 32;

    for (int base = blockIdx.x * 32 + warp * 4; base < NN; base += gridDim.x * 32) {
#pragma unroll
        for (int mm = 0; mm < 4; mm++) {
            int n = base + mm;
            float4 v = make_float4(0.f, 0.f, 0.f, 0.f);
            if (n < NN) {
                float4 g = geo4[(size_t)n * 32 + lane];
                float4 t = trn4[(size_t)n * 32 + lane];
                float4 c = cat4[(size_t)n * 32 + lane];
                v.x = b0 * g.x + b1 * t.x + b2 * c.x;
                v.y = b0 * g.y + b1 * t.y + b2 * c.y;
                v.z = b0 * g.z + b1 * t.z + b2 * c.z;
                v.w = b0 * g.w + b1 * t.w + b2 * c.w;
            }
            u64* zp = Zw + mm * DD + lane * 4;
            zp[0] = pack2(v.x); zp[1] = pack2(v.y); zp[2] = pack2(v.z); zp[3] = pack2(v.w);
        }
        __syncwarp();

        u64 acc[4][2];
#pragma unroll
        for (int mm = 0; mm < 4; mm++) { acc[mm][0] = 0ull; acc[mm][1] = 0ull; }

#pragma unroll 4
        for (int k = 0; k < DD; k++) {
            ulonglong2 wv = Wv[k * 32 + lane];
#pragma unroll
            for (int mm = 0; mm < 4; mm++) {
                u64 zz = Zw[mm * DD + k];
                ffma2(acc[mm][0], zz, wv.x);
                ffma2(acc[mm][1], zz, wv.y);
            }
        }

#pragma unroll
        for (int mm = 0; mm < 4; mm++) {
            int n = base + mm;
            if (n < NN) {
                float2 p0 = unpack2(acc[mm][0]);
                float2 p1 = unpack2(acc[mm][1]);
                p0.x = (p0.x >= 0.f) ? p0.x : 0.2f * p0.x;
                p0.y = (p0.y >= 0.f) ? p0.y : 0.2f * p0.y;
                p1.x = (p1.x >= 0.f) ? p1.x : 0.2f * p1.x;
                p1.y = (p1.y >= 0.f) ? p1.y : 0.2f * p1.y;
                ((float2*)out)[n * 64 + lane] = p0;
                ((float2*)out)[n * 64 + 32 + lane] = p1;
            }
        }
        __syncwarp();
    }
}

// ---------------- launcher -------------------------------------------------------------
extern "C" void kernel_launch(void* const* d_in, const int* in_sizes, int n_in,
                              void* d_out, int out_size) {
    const float* feat = (const float*)d_in[0];
    const float* Wt   = (const float*)d_in[1];
    const float* w1   = (const float*)d_in[2];
    const float* b1   = (const float*)d_in[3];
    const float* w2   = (const float*)d_in[4];
    const float* tw   = (const float*)d_in[5];
    const int* gs = (const int*)d_in[6];
    const int* gd = (const int*)d_in[7];
    const int* cs = (const int*)d_in[8];
    const int* cd = (const int*)d_in[9];
    const int* ts = (const int*)d_in[10];
    const int* td = (const int*)d_in[11];
    float* out = (float*)d_out;

    const int SMEM_FUSE = 65536 + 32768;
    cudaFuncSetAttribute(att_mma_kernel, cudaFuncAttributeMaxDynamicSharedMemorySize, SMEM_ATT);
    cudaFuncSetAttribute(fuse_kernel, cudaFuncAttributeMaxDynamicSharedMemorySize, SMEM_FUSE);

    zero_kernel<<<(3 * NN + 255) / 256, 256>>>();
    wcomb_kernel<<<256, 256>>>(w1, Wt);
    fill_kernel<<<(3 * NE + 255) / 256, 256>>>(gs, gd, cs, cd, ts, td, tw);
    gather_kernel<<<2048, 256>>>(feat);
    fixup_kernel<<<1, 256>>>(feat);
    att_mma_kernel<<<148, 256, SMEM_ATT>>>(b1, w2);
    fuse_kernel<<<296, 256, SMEM_FUSE>>>(Wt, out);
}

// round 6
// speedup vs baseline: 3.4956x; 1.0276x over previous
#include <cuda_runtime.h>
#include <cuda_bf16.h>
#include <cuda_fp16.h>
#include <cstdint>
#include <math.h>

#define NN 100000
#define NE 600000
#define DD 128
#define CAP 64
#define NTILES 782                 // ceil(100000/128)
#define TILES_TOTAL (3 * NTILES)
#define OVF_MAX 4096

typedef unsigned long long u64;
typedef unsigned int u32;

// ---------------- device scratch ------------------------------------------------------
__device__ float g_agg[3 * NN * DD];          // f32 aggregates: [geo, trans, cat]
__device__ __nv_bfloat16 g_aggh[3 * NN * DD]; // bf16 copy for att staging
__device__ u32 g_deg[3 * NN];
__device__ int g_bucket[3 * NN * CAP];
__device__ float g_bw[NN * CAP];              // weights for trans buckets
__device__ float g_wcomb[512 * DD];           // W1 @ W_tran
__device__ float g_wsum[3];
__device__ u32 g_ovf_cnt;
__device__ int g_ovf[OVF_MAX * 4];            // rel, dst, src, w-bits

// ---------------- small PTX helpers ---------------------------------------------------
__device__ __forceinline__ u64 pack2(float x) {
    u64 r; asm("mov.b64 %0, {%1, %1};" : "=l"(r) : "f"(x)); return r;
}
__device__ __forceinline__ void ffma2(u64& d, u64 a, u64 b) {
    asm("fma.rn.f32x2 %0, %1, %2, %0;" : "+l"(d) : "l"(a), "l"(b));
}
__device__ __forceinline__ float2 unpack2(u64 v) {
    float2 f; asm("mov.b64 {%0, %1}, %2;" : "=f"(f.x), "=f"(f.y) : "l"(v)); return f;
}
__device__ __forceinline__ __half2 tanh2(__half2 x) {
    u32 xi = *(u32*)&x, yi;
    asm("tanh.approx.f16x2 %0, %1;" : "=r"(yi) : "r"(xi));
    return *(__half2*)&yi;
}
__device__ __forceinline__ u32 smem_u32(const void* p) {
    u32 a; asm("{ .reg .u64 t; cvta.to.shared.u64 t, %1; cvt.u32.u64 %0, t; }" : "=r"(a) : "l"(p));
    return a;
}
__device__ __forceinline__ void ldsm_x4(u32& r0, u32& r1, u32& r2, u32& r3, u32 addr) {
    asm volatile("ldmatrix.sync.aligned.m8n8.x4.shared.b16 {%0,%1,%2,%3}, [%4];"
                 : "=r"(r0), "=r"(r1), "=r"(r2), "=r"(r3) : "r"(addr));
}
__device__ __forceinline__ void ldsm_x2(u32& r0, u32& r1, u32 addr) {
    asm volatile("ldmatrix.sync.aligned.m8n8.x2.shared.b16 {%0,%1}, [%2];"
                 : "=r"(r0), "=r"(r1) : "r"(addr));
}
__device__ __forceinline__ void mma_16816(float* c, u32 a0, u32 a1, u32 a2, u32 a3,
                                          u32 b0, u32 b1) {
    asm volatile(
        "mma.sync.aligned.m16n8k16.row.col.f32.bf16.bf16.f32 "
        "{%0,%1,%2,%3}, {%4,%5,%6,%7}, {%8,%9}, {%0,%1,%2,%3};"
        : "+f"(c[0]), "+f"(c[1]), "+f"(c[2]), "+f"(c[3])
        : "r"(a0), "r"(a1), "r"(a2), "r"(a3), "r"(b0), "r"(b1));
}
__device__ __forceinline__ u64 pack_bf16x4(float x, float y, float z, float w) {
    __nv_bfloat162 p0 = __floats2bfloat162_rn(x, y);
    __nv_bfloat162 p1 = __floats2bfloat162_rn(z, w);
    return (u64)(*(u32*)&p0) | ((u64)(*(u32*)&p1) << 32);
}

// ---------------- stage [128x128] f32 weights into paired-f32x2 smem layout -----------
__device__ __forceinline__ void stage_w128(float* Ws, const float* __restrict__ Wsrc,
                                           int tid, int nthreads) {
    for (int idx = tid; idx < DD * DD; idx += nthreads) {
        int j = idx >> 7, k = idx & 127;
        int l, c;
        if (j < 64) { l = j >> 1; c = j & 1; }
        else        { l = (j - 64) >> 1; c = 2 + ((j - 64) & 1); }
        Ws[(k * 32 + l) * 4 + c] = Wsrc[idx];
    }
}

// ---------------- kernel: zero counters ------------------------------------------------
__global__ void zero_kernel() {
    int i = blockIdx.x * blockDim.x + threadIdx.x;
    int stride = gridDim.x * blockDim.x;
    for (int k = i; k < 3 * NN; k += stride) g_deg[k] = 0u;
    if (i < 3) g_wsum[i] = 0.f;
    if (i == 3) g_ovf_cnt = 0u;
}

// ---------------- kernel: Wcomb = W1 @ W_tran ------------------------------------------
__global__ __launch_bounds__(256) void wcomb_kernel(const float* __restrict__ W1,
                                                    const float* __restrict__ Wt) {
    int idx = blockIdx.x * 256 + threadIdx.x;   // 65536 outputs
    int h = idx >> 7, j = idx & 127;
    float acc = 0.f;
#pragma unroll 8
    for (int k = 0; k < DD; k++)
        acc += W1[h * DD + k] * Wt[k * DD + j];
    g_wcomb[idx] = acc;
}

// ---------------- kernel: fill destination buckets -------------------------------------
__global__ __launch_bounds__(256) void fill_kernel(
    const int* __restrict__ gs, const int* __restrict__ gd,
    const int* __restrict__ cs, const int* __restrict__ cd,
    const int* __restrict__ ts, const int* __restrict__ td,
    const float* __restrict__ tw) {
    int i = blockIdx.x * blockDim.x + threadIdx.x;
    if (i >= 3 * NE) return;
    int rel = i / NE;
    int e = i - rel * NE;
    int src, dst; float w = 1.f;
    if (rel == 0)      { src = gs[e]; dst = gd[e]; }
    else if (rel == 1) { src = cs[e]; dst = cd[e]; }
    else               { src = ts[e]; dst = td[e]; w = tw[e]; }

    u32 pos = atomicAdd(&g_deg[rel * NN + dst], 1u);
    if (pos < CAP) {
        g_bucket[(rel * NN + dst) * CAP + pos] = src;
        if (rel == 2) g_bw[dst * CAP + pos] = w;
    } else {
        u32 o = atomicAdd(&g_ovf_cnt, 1u);
        if (o < OVF_MAX) {
            g_ovf[o * 4 + 0] = rel;
            g_ovf[o * 4 + 1] = dst;
            g_ovf[o * 4 + 2] = src;
            g_ovf[o * 4 + 3] = __float_as_int(w);
        }
    }
}

// ---------------- kernel: per-destination gather-sum (uniform-LDG indices, MLP=8) -----
__global__ __launch_bounds__(256) void gather_kernel(const float* __restrict__ feat) {
    int warps_total = gridDim.x * (blockDim.x >> 5);
    int gw0 = blockIdx.x * (blockDim.x >> 5) + (threadIdx.x >> 5);
    int lane = threadIdx.x & 31;
    const float4* f4 = (const float4*)feat;

    for (int gw = gw0; gw < 3 * NN; gw += warps_total) {
        int rel = gw / NN, dst = gw - rel * NN;

        u32 d = g_deg[rel * NN + dst];
        u32 lim = d < CAP ? d : CAP;
        const int4* bkv = (const int4*)&g_bucket[(size_t)(rel * NN + dst) * CAP];

        float4 acc = make_float4(0.f, 0.f, 0.f, 0.f);

        if (rel != 2) {
            for (u32 e = 0; e < lim; e += 8) {
                // Uniform index loads: 2x LDG.128 broadcast per batch of 8 rows
                int4 ia = bkv[e >> 2];
                int4 ib = bkv[(e >> 2) + 1];
                int si[8] = {ia.x, ia.y, ia.z, ia.w, ib.x, ib.y, ib.z, ib.w};
                float4 v[8];
#pragma unroll
                for (int j = 0; j < 8; j++)
                    v[j] = (e + j < lim) ? f4[(size_t)si[j] * 32 + lane]
                                         : make_float4(0.f, 0.f, 0.f, 0.f);
#pragma unroll
                for (int j = 0; j < 8; j++) {
                    acc.x += v[j].x; acc.y += v[j].y; acc.z += v[j].z; acc.w += v[j].w;
                }
            }
            float sc = 1.f / fmaxf((float)d, 1.f);
            acc.x *= sc; acc.y *= sc; acc.z *= sc; acc.w *= sc;
        } else {
            const float4* bwv = (const float4*)&g_bw[(size_t)dst * CAP];
            for (u32 e = 0; e < lim; e += 8) {
                int4 ia = bkv[e >> 2];
                int4 ib = bkv[(e >> 2) + 1];
                float4 wa = bwv[e >> 2];
                float4 wb = bwv[(e >> 2) + 1];
                int si[8] = {ia.x, ia.y, ia.z, ia.w, ib.x, ib.y, ib.z, ib.w};
                float wi[8] = {wa.x, wa.y, wa.z, wa.w, wb.x, wb.y, wb.z, wb.w};
                float4 v[8];
#pragma unroll
                for (int j = 0; j < 8; j++) {
                    bool p = e + j < lim;
                    v[j] = p ? f4[(size_t)si[j] * 32 + lane]
                             : make_float4(0.f, 0.f, 0.f, 0.f);
                    if (!p) wi[j] = 0.f;
                }
#pragma unroll
                for (int j = 0; j < 8; j++) {
                    acc.x += v[j].x * wi[j];
                    acc.y += v[j].y * wi[j];
                    acc.z += v[j].z * wi[j];
                    acc.w += v[j].w * wi[j];
                }
            }
        }

        size_t row = (size_t)(rel * NN + dst);
        ((float4*)g_agg)[row * 32 + lane] = acc;
        ((u64*)g_aggh)[row * 32 + lane] = pack_bf16x4(acc.x, acc.y, acc.z, acc.w);
    }
}

// ---------------- kernel: exact fixup for bucket overflow (expected count: 0) ----------
__global__ void fixup_kernel(const float* __restrict__ feat) {
    u32 cnt = g_ovf_cnt;
    if (cnt > OVF_MAX) cnt = OVF_MAX;
    int warp = threadIdx.x >> 5, lane = threadIdx.x & 31;
    for (u32 o = warp; o < cnt; o += 8) {
        int rel = g_ovf[o * 4 + 0];
        int dst = g_ovf[o * 4 + 1];
        int src = g_ovf[o * 4 + 2];
        float w = __int_as_float(g_ovf[o * 4 + 3]);
        float sc = (rel == 2) ? w : 1.f / fmaxf((float)g_deg[rel * NN + dst], 1.f);
        float4 v = ((const float4*)feat)[(size_t)src * 32 + lane];
        float* p = g_agg + ((size_t)(rel * NN + dst)) * DD + lane * 4;
        asm volatile("red.global.add.v4.f32 [%0], {%1,%2,%3,%4};"
                     :: "l"(p), "f"(v.x * sc), "f"(v.y * sc), "f"(v.z * sc), "f"(v.w * sc)
                     : "memory");
    }
}

// ---------------- kernel: attention via mma.sync bf16 HMMA -----------------------------
#define ATT_LDA 136      // padded row stride (bf16 elems); 272 B
#define SM_B   0
#define SM_A   139264
#define SM_B1  174080
#define SM_W2  176128
#define SMEM_ATT 178176

__global__ __launch_bounds__(256) void att_mma_kernel(const float* __restrict__ B1,
                                                      const float* __restrict__ W2) {
    extern __shared__ char smem[];
    u32 sb = smem_u32(smem);
    int tid = threadIdx.x, wid = tid >> 5, lane = tid & 31;

    // Stage B = Wcomb (f32 -> bf16), b1, w2
    for (int i = tid; i < 512 * 32; i += 256) {
        int j = i >> 5, q = i & 31;
        float4 v = ((const float4*)g_wcomb)[i];
        *(u64*)(smem + SM_B + (j * ATT_LDA + q * 4) * 2) = pack_bf16x4(v.x, v.y, v.z, v.w);
    }
    for (int i = tid; i < 512; i += 256) {
        ((float*)(smem + SM_B1))[i] = B1[i];
        ((float*)(smem + SM_W2))[i] = W2[i];
    }
    __syncthreads();

    const float* b1s = (const float*)(smem + SM_B1);
    const float* w2s = (const float*)(smem + SM_W2);

    // Per-thread tile-invariant half2 bias/weight pairs for the epilogue
    __half2 bh[8], wh[8];
#pragma unroll
    for (int nn = 0; nn < 8; nn++) {
        int j0 = (wid << 6) + nn * 8 + ((lane & 3) << 1);
        bh[nn] = __floats2half2_rn(b1s[j0], b1s[j0 + 1]);
        wh[nn] = __floats2half2_rn(w2s[j0], w2s[j0 + 1]);
    }

    float racc[3] = {0.f, 0.f, 0.f};

    for (int t = blockIdx.x; t < TILES_TOTAL; t += gridDim.x) {
        int rel = t / NTILES;
        int tile = t - rel * NTILES;
        int base = tile * 128;

        // Stage A: 128 node rows of precomputed bf16 aggregates
        for (int i = tid; i < 128 * 16; i += 256) {
            int row = i >> 4, q = i & 15;
            int node = base + row;
            uint4 v = make_uint4(0u, 0u, 0u, 0u);
            if (node < NN)
                v = ((const uint4*)g_aggh)[(size_t)(rel * NN + node) * 16 + q];
            *(uint4*)(smem + SM_A + row * (ATT_LDA * 2) + q * 16) = v;
        }
        __syncthreads();

        float ps = 0.f;
#pragma unroll
        for (int mp = 0; mp < 4; mp++) {
            int m0 = mp * 32;
            float acc[2][8][4];
#pragma unroll
            for (int s = 0; s < 2; s++)
#pragma unroll
                for (int n = 0; n < 8; n++)
#pragma unroll
                    for (int ee = 0; ee < 4; ee++) acc[s][n][ee] = 0.f;

#pragma unroll
            for (int kk = 0; kk < 8; kk++) {
                u32 a0[4], a1[4];
                u32 arow0 = m0 + (lane & 15);
                u32 acol = kk * 16 + ((lane >> 4) << 3);
                ldsm_x4(a0[0], a0[1], a0[2], a0[3],
                        sb + SM_A + (arow0 * ATT_LDA + acol) * 2);
                ldsm_x4(a1[0], a1[1], a1[2], a1[3],
                        sb + SM_A + ((arow0 + 16) * ATT_LDA + acol) * 2);

#pragma unroll
                for (int nn = 0; nn < 8; nn++) {
                    u32 b0, b1r;
                    u32 brow = (wid << 6) + nn * 8 + (lane & 7);
                    u32 bcol = kk * 16 + (((lane >> 3) & 1) << 3);
                    ldsm_x2(b0, b1r, sb + SM_B + (brow * ATT_LDA + bcol) * 2);
                    mma_16816(acc[0][nn], a0[0], a0[1], a0[2], a0[3], b0, b1r);
                    mma_16816(acc[1][nn], a1[0], a1[1], a1[2], a1[3], b0, b1r);
                }
            }

            // Epilogue (f16x2): hsum += wh * tanh(acc + bh), masked on node validity
            __half2 hsum = __floats2half2_rn(0.f, 0.f);
            bool v0 = (base + m0 + (lane >> 2)) < NN;
            bool v1 = (base + m0 + 8 + (lane >> 2)) < NN;
            bool v2 = (base + m0 + 16 + (lane >> 2)) < NN;
            bool v3 = (base + m0 + 24 + (lane >> 2)) < NN;
#pragma unroll
            for (int nn = 0; nn < 8; nn++) {
#pragma unroll
                for (int s = 0; s < 2; s++) {
                    const float* c = acc[s][nn];
                    bool pa = s ? v2 : v0;
                    bool pb = s ? v3 : v1;
                    if (pa) {
                        __half2 x = __hadd2(__floats2half2_rn(c[0], c[1]), bh[nn]);
                        hsum = __hfma2(tanh2(x), wh[nn], hsum);
                    }
                    if (pb) {
                        __half2 x = __hadd2(__floats2half2_rn(c[2], c[3]), bh[nn]);
                        hsum = __hfma2(tanh2(x), wh[nn], hsum);
                    }
                }
            }
            float2 hs = __half22float2(hsum);
            ps += hs.x + hs.y;
        }
        racc[rel] += ps;
        __syncthreads();
    }

#pragma unroll
    for (int o = 16; o; o >>= 1) {
        racc[0] += __shfl_xor_sync(0xffffffffu, racc[0], o);
        racc[1] += __shfl_xor_sync(0xffffffffu, racc[1], o);
        racc[2] += __shfl_xor_sync(0xffffffffu, racc[2], o);
    }
    if (lane == 0) {
        atomicAdd(&g_wsum[0], racc[0]);
        atomicAdd(&g_wsum[1], racc[1]);
        atomicAdd(&g_wsum[2], racc[2]);
    }
}

// ---------------- kernel: fuse = leaky((b0*geo + b1*trans + b2*cat) @ Wt^T) ------------
__global__ __launch_bounds__(256) void fuse_kernel(const float* __restrict__ Wt,
                                                   float* __restrict__ out) {
    extern __shared__ char smem[];
    float* Ws = (float*)smem;                  // 65536 B
    u64* Zs = (u64*)(smem + 65536);            // 32768 B
    int tid = threadIdx.x;
    stage_w128(Ws, Wt, tid, 256);
    __syncthreads();

    float w0 = g_wsum[0] * (1.f / NN);
    float w1 = g_wsum[1] * (1.f / NN);
    float w2 = g_wsum[2] * (1.f / NN);
    float m = fmaxf(w0, fmaxf(w1, w2));
    float e0 = expf(w0 - m), e1 = expf(w1 - m), e2 = expf(w2 - m);
    float inv = 1.f / (e0 + e1 + e2);
    float b0 = e0 * inv, b1 = e1 * inv, b2 = e2 * inv;

    const ulonglong2* Wv = (const ulonglong2*)Ws;
    int warp = tid >> 5, lane = tid & 31;
    u64* Zw = Zs + warp * 4 * DD;
    const float4* geo4 = (const float4*)g_agg;
    const float4* trn4 = geo4 + (size_t)NN * 32;
    const float4* cat4 = trn4 + (size_t)NN * 32;

    for (int base = blockIdx.x * 32 + warp * 4; base < NN; base += gridDim.x * 32) {
#pragma unroll
        for (int mm = 0; mm < 4; mm++) {
            int n = base + mm;
            float4 v = make_float4(0.f, 0.f, 0.f, 0.f);
            if (n < NN) {
                float4 g = geo4[(size_t)n * 32 + lane];
                float4 t = trn4[(size_t)n * 32 + lane];
                float4 c = cat4[(size_t)n * 32 + lane];
                v.x = b0 * g.x + b1 * t.x + b2 * c.x;
                v.y = b0 * g.y + b1 * t.y + b2 * c.y;
                v.z = b0 * g.z + b1 * t.z + b2 * c.z;
                v.w = b0 * g.w + b1 * t.w + b2 * c.w;
            }
            u64* zp = Zw + mm * DD + lane * 4;
            zp[0] = pack2(v.x); zp[1] = pack2(v.y); zp[2] = pack2(v.z); zp[3] = pack2(v.w);
        }
        __syncwarp();

        u64 acc[4][2];
#pragma unroll
        for (int mm = 0; mm < 4; mm++) { acc[mm][0] = 0ull; acc[mm][1] = 0ull; }

#pragma unroll 4
        for (int k = 0; k < DD; k++) {
            ulonglong2 wv = Wv[k * 32 + lane];
#pragma unroll
            for (int mm = 0; mm < 4; mm++) {
                u64 zz = Zw[mm * DD + k];
                ffma2(acc[mm][0], zz, wv.x);
                ffma2(acc[mm][1], zz, wv.y);
            }
        }

#pragma unroll
        for (int mm = 0; mm < 4; mm++) {
            int n = base + mm;
            if (n < NN) {
                float2 p0 = unpack2(acc[mm][0]);
                float2 p1 = unpack2(acc[mm][1]);
                p0.x = (p0.x >= 0.f) ? p0.x : 0.2f * p0.x;
                p0.y = (p0.y >= 0.f) ? p0.y : 0.2f * p0.y;
                p1.x = (p1.x >= 0.f) ? p1.x : 0.2f * p1.x;
                p1.y = (p1.y >= 0.f) ? p1.y : 0.2f * p1.y;
                ((float2*)out)[n * 64 + lane] = p0;
                ((float2*)out)[n * 64 + 32 + lane] = p1;
            }
        }
        __syncwarp();
    }
}

// ---------------- launcher -------------------------------------------------------------
extern "C" void kernel_launch(void* const* d_in, const int* in_sizes, int n_in,
                              void* d_out, int out_size) {
    const float* feat = (const float*)d_in[0];
    const float* Wt   = (const float*)d_in[1];
    const float* w1   = (const float*)d_in[2];
    const float* b1   = (const float*)d_in[3];
    const float* w2   = (const float*)d_in[4];
    const float* tw   = (const float*)d_in[5];
    const int* gs = (const int*)d_in[6];
    const int* gd = (const int*)d_in[7];
    const int* cs = (const int*)d_in[8];
    const int* cd = (const int*)d_in[9];
    const int* ts = (const int*)d_in[10];
    const int* td = (const int*)d_in[11];
    float* out = (float*)d_out;

    const int SMEM_FUSE = 65536 + 32768;
    cudaFuncSetAttribute(att_mma_kernel, cudaFuncAttributeMaxDynamicSharedMemorySize, SMEM_ATT);
    cudaFuncSetAttribute(fuse_kernel, cudaFuncAttributeMaxDynamicSharedMemorySize, SMEM_FUSE);

    zero_kernel<<<(3 * NN + 255) / 256, 256>>>();
    wcomb_kernel<<<256, 256>>>(w1, Wt);
    fill_kernel<<<(3 * NE + 255) / 256, 256>>>(gs, gd, cs, cd, ts, td, tw);
    gather_kernel<<<2048, 256>>>(feat);
    fixup_kernel<<<1, 256>>>(feat);
    att_mma_kernel<<<148, 256, SMEM_ATT>>>(b1, w2);
    fuse_kernel<<<296, 256, SMEM_FUSE>>>(Wt, out);
}

// round 7
// speedup vs baseline: 3.6507x; 1.0444x over previous
#include <cuda_runtime.h>
#include <cuda_bf16.h>
#include <cuda_fp16.h>
#include <cstdint>
#include <math.h>

#define NN 100000
#define NE 600000
#define DD 128
#define CAP 64
#define NTILES 782                 // ceil(100000/128)
#define TILES_TOTAL (3 * NTILES)
#define OVF_MAX 4096

typedef unsigned long long u64;
typedef unsigned int u32;

// ---------------- device scratch ------------------------------------------------------
__device__ float g_agg[3 * NN * DD];          // f32 aggregates: [geo, trans, cat]
__device__ __nv_bfloat16 g_aggh[3 * NN * DD]; // bf16 copy for att staging
__device__ u32 g_deg[3 * NN];
__device__ int g_bucket[3 * NN * CAP];
__device__ float g_bw[NN * CAP];              // weights for trans buckets
__device__ float g_wcomb[512 * DD];           // W1 @ W_tran
__device__ float g_wsum[3];
__device__ u32 g_ovf_cnt;
__device__ int g_ovf[OVF_MAX * 4];            // rel, dst, src, w-bits

// ---------------- small PTX helpers ---------------------------------------------------
__device__ __forceinline__ u64 pack2(float x) {
    u64 r; asm("mov.b64 %0, {%1, %1};" : "=l"(r) : "f"(x)); return r;
}
__device__ __forceinline__ void ffma2(u64& d, u64 a, u64 b) {
    asm("fma.rn.f32x2 %0, %1, %2, %0;" : "+l"(d) : "l"(a), "l"(b));
}
__device__ __forceinline__ float2 unpack2(u64 v) {
    float2 f; asm("mov.b64 {%0, %1}, %2;" : "=f"(f.x), "=f"(f.y) : "l"(v)); return f;
}
__device__ __forceinline__ __half2 tanh2(__half2 x) {
    u32 xi = *(u32*)&x, yi;
    asm("tanh.approx.f16x2 %0, %1;" : "=r"(yi) : "r"(xi));
    return *(__half2*)&yi;
}
__device__ __forceinline__ u32 smem_u32(const void* p) {
    u32 a; asm("{ .reg .u64 t; cvta.to.shared.u64 t, %1; cvt.u32.u64 %0, t; }" : "=r"(a) : "l"(p));
    return a;
}
__device__ __forceinline__ void ldsm_x4(u32& r0, u32& r1, u32& r2, u32& r3, u32 addr) {
    asm volatile("ldmatrix.sync.aligned.m8n8.x4.shared.b16 {%0,%1,%2,%3}, [%4];"
                 : "=r"(r0), "=r"(r1), "=r"(r2), "=r"(r3) : "r"(addr));
}
__device__ __forceinline__ void mma_16816(float* c, u32 a0, u32 a1, u32 a2, u32 a3,
                                          u32 b0, u32 b1) {
    asm volatile(
        "mma.sync.aligned.m16n8k16.row.col.f32.bf16.bf16.f32 "
        "{%0,%1,%2,%3}, {%4,%5,%6,%7}, {%8,%9}, {%0,%1,%2,%3};"
        : "+f"(c[0]), "+f"(c[1]), "+f"(c[2]), "+f"(c[3])
        : "r"(a0), "r"(a1), "r"(a2), "r"(a3), "r"(b0), "r"(b1));
}
__device__ __forceinline__ u64 pack_bf16x4(float x, float y, float z, float w) {
    __nv_bfloat162 p0 = __floats2bfloat162_rn(x, y);
    __nv_bfloat162 p1 = __floats2bfloat162_rn(z, w);
    return (u64)(*(u32*)&p0) | ((u64)(*(u32*)&p1) << 32);
}

// ---------------- stage [128x128] f32 weights into paired-f32x2 smem layout -----------
__device__ __forceinline__ void stage_w128(float* Ws, const float* __restrict__ Wsrc,
                                           int tid, int nthreads) {
    for (int idx = tid; idx < DD * DD; idx += nthreads) {
        int j = idx >> 7, k = idx & 127;
        int l, c;
        if (j < 64) { l = j >> 1; c = j & 1; }
        else        { l = (j - 64) >> 1; c = 2 + ((j - 64) & 1); }
        Ws[(k * 32 + l) * 4 + c] = Wsrc[idx];
    }
}

// ---------------- kernel: zero counters ------------------------------------------------
__global__ void zero_kernel() {
    int i = blockIdx.x * blockDim.x + threadIdx.x;
    int stride = gridDim.x * blockDim.x;
    for (int k = i; k < 3 * NN; k += stride) g_deg[k] = 0u;
    if (i < 3) g_wsum[i] = 0.f;
    if (i == 3) g_ovf_cnt = 0u;
}

// ---------------- kernel: Wcomb = W1 @ W_tran ------------------------------------------
__global__ __launch_bounds__(256) void wcomb_kernel(const float* __restrict__ W1,
                                                    const float* __restrict__ Wt) {
    int idx = blockIdx.x * 256 + threadIdx.x;   // 65536 outputs
    int h = idx >> 7, j = idx & 127;
    float acc = 0.f;
#pragma unroll 8
    for (int k = 0; k < DD; k++)
        acc += W1[h * DD + k] * Wt[k * DD + j];
    g_wcomb[idx] = acc;
}

// ---------------- kernel: fill destination buckets -------------------------------------
__global__ __launch_bounds__(256) void fill_kernel(
    const int* __restrict__ gs, const int* __restrict__ gd,
    const int* __restrict__ cs, const int* __restrict__ cd,
    const int* __restrict__ ts, const int* __restrict__ td,
    const float* __restrict__ tw) {
    int i = blockIdx.x * blockDim.x + threadIdx.x;
    if (i >= 3 * NE) return;
    int rel = i / NE;
    int e = i - rel * NE;
    int src, dst; float w = 1.f;
    if (rel == 0)      { src = gs[e]; dst = gd[e]; }
    else if (rel == 1) { src = cs[e]; dst = cd[e]; }
    else               { src = ts[e]; dst = td[e]; w = tw[e]; }

    u32 pos = atomicAdd(&g_deg[rel * NN + dst], 1u);
    if (pos < CAP) {
        g_bucket[(rel * NN + dst) * CAP + pos] = src;
        if (rel == 2) g_bw[dst * CAP + pos] = w;
    } else {
        u32 o = atomicAdd(&g_ovf_cnt, 1u);
        if (o < OVF_MAX) {
            g_ovf[o * 4 + 0] = rel;
            g_ovf[o * 4 + 1] = dst;
            g_ovf[o * 4 + 2] = src;
            g_ovf[o * 4 + 3] = __float_as_int(w);
        }
    }
}

// ---------------- kernel: per-destination gather-sum (metadata pipelined) -------------
__global__ __launch_bounds__(256) void gather_kernel(const float* __restrict__ feat) {
    const int warps_total = gridDim.x * 8;
    int gw = blockIdx.x * 8 + (threadIdx.x >> 5);
    const int lane = threadIdx.x & 31;
    const float4* f4 = (const float4*)feat;
    const int4* bk4 = (const int4*)g_bucket;
    const float4* bw4 = (const float4*)g_bw;

    if (gw >= 3 * NN) return;

    // Prefetch metadata for the first destination
    u32 dN = g_deg[gw];
    int4 iaN = bk4[(u32)gw * 16];
    int4 ibN = bk4[(u32)gw * 16 + 1];
    {
        int dst0 = gw % NN;
        // fall through below (weights prefetched in-loop pattern)
        (void)dst0;
    }
    int relN = gw / NN;
    int dstN = gw - relN * NN;
    float4 waN = bw4[(u32)dstN * 16];
    float4 wbN = bw4[(u32)dstN * 16 + 1];

    while (true) {
        u32 d = dN; int4 ia = iaN, ib = ibN; float4 wa = waN, wb = wbN;
        int rel = relN, dst = dstN;
        int gwn = gw + warps_total;
        bool hn = gwn < 3 * NN;
        if (hn) {
            // Prefetch next destination's metadata (overlaps with row gathers below)
            dN = g_deg[gwn];
            iaN = bk4[(u32)gwn * 16];
            ibN = bk4[(u32)gwn * 16 + 1];
            relN = gwn / NN;
            dstN = gwn - relN * NN;
            waN = bw4[(u32)dstN * 16];
            wbN = bw4[(u32)dstN * 16 + 1];
        }

        u32 lim = d < CAP ? d : CAP;
        bool wtd = (rel == 2);
        float4 acc = make_float4(0.f, 0.f, 0.f, 0.f);

        {
            int si[8] = {ia.x, ia.y, ia.z, ia.w, ib.x, ib.y, ib.z, ib.w};
            float wi[8] = {wa.x, wa.y, wa.z, wa.w, wb.x, wb.y, wb.z, wb.w};
            float4 v[8]; float ww[8];
#pragma unroll
            for (int j = 0; j < 8; j++) {
                bool p = (u32)j < lim;
                u32 off = (u32)si[j] * 32u + lane;
                v[j] = p ? f4[off] : make_float4(0.f, 0.f, 0.f, 0.f);
                ww[j] = p ? (wtd ? wi[j] : 1.f) : 0.f;
            }
#pragma unroll
            for (int j = 0; j < 8; j++) {
                acc.x += v[j].x * ww[j];
                acc.y += v[j].y * ww[j];
                acc.z += v[j].z * ww[j];
                acc.w += v[j].w * ww[j];
            }
        }
        // Rare tail: degree > 8
        for (u32 e = 8; e < lim; e += 8) {
            int4 ja = bk4[(u32)gw * 16 + (e >> 2)];
            int4 jb = bk4[(u32)gw * 16 + (e >> 2) + 1];
            float4 ua = bw4[(u32)dst * 16 + (e >> 2)];
            float4 ub = bw4[(u32)dst * 16 + (e >> 2) + 1];
            int si[8] = {ja.x, ja.y, ja.z, ja.w, jb.x, jb.y, jb.z, jb.w};
            float wi[8] = {ua.x, ua.y, ua.z, ua.w, ub.x, ub.y, ub.z, ub.w};
            float4 v[8]; float ww[8];
#pragma unroll
            for (int j = 0; j < 8; j++) {
                bool p = e + j < lim;
                u32 off = (u32)si[j] * 32u + lane;
                v[j] = p ? f4[off] : make_float4(0.f, 0.f, 0.f, 0.f);
                ww[j] = p ? (wtd ? wi[j] : 1.f) : 0.f;
            }
#pragma unroll
            for (int j = 0; j < 8; j++) {
                acc.x += v[j].x * ww[j];
                acc.y += v[j].y * ww[j];
                acc.z += v[j].z * ww[j];
                acc.w += v[j].w * ww[j];
            }
        }

        float sc = wtd ? 1.f : 1.f / fmaxf((float)d, 1.f);
        acc.x *= sc; acc.y *= sc; acc.z *= sc; acc.w *= sc;

        ((float4*)g_agg)[(u32)gw * 32 + lane] = acc;
        ((u64*)g_aggh)[(u32)gw * 32 + lane] = pack_bf16x4(acc.x, acc.y, acc.z, acc.w);

        if (!hn) break;
        gw = gwn;
    }
}

// ---------------- kernel: exact fixup for bucket overflow (expected count: 0) ----------
__global__ void fixup_kernel(const float* __restrict__ feat) {
    u32 cnt = g_ovf_cnt;
    if (cnt > OVF_MAX) cnt = OVF_MAX;
    int warp = threadIdx.x >> 5, lane = threadIdx.x & 31;
    for (u32 o = warp; o < cnt; o += 8) {
        int rel = g_ovf[o * 4 + 0];
        int dst = g_ovf[o * 4 + 1];
        int src = g_ovf[o * 4 + 2];
        float w = __int_as_float(g_ovf[o * 4 + 3]);
        float sc = (rel == 2) ? w : 1.f / fmaxf((float)g_deg[rel * NN + dst], 1.f);
        float4 v = ((const float4*)feat)[(size_t)src * 32 + lane];
        float* p = g_agg + ((size_t)(rel * NN + dst)) * DD + lane * 4;
        asm volatile("red.global.add.v4.f32 [%0], {%1,%2,%3,%4};"
                     :: "l"(p), "f"(v.x * sc), "f"(v.y * sc), "f"(v.z * sc), "f"(v.w * sc)
                     : "memory");
        // NOTE: overflow rows were scaled by deg inside gather only for the first CAP
        // edges; with CAP=64 and Poisson(6) degrees this path is statistically absent.
    }
}

// ---------------- kernel: attention, cp.async double-buffered A + HMMA ----------------
// smem: A0 @0 (34816), A1 @34816, B = Wcomb bf16 [512 x 136] @69632 (139264),
// b1 @208896 (2048), w2 @210944 (2048). Total 212992.
#define ATT_LDA 136
#define A_BYTES 34816
#define SM_A0  0
#define SM_B   69632
#define SM_B1  208896
#define SM_W2  210944
#define SMEM_ATT 212992

__global__ __launch_bounds__(256) void att_mma_kernel(const float* __restrict__ B1,
                                                      const float* __restrict__ W2) {
    extern __shared__ char smem[];
    u32 sb = smem_u32(smem);
    int tid = threadIdx.x, wid = tid >> 5, lane = tid & 31;

    // Stage B = Wcomb (f32 -> bf16), b1, w2
    for (int i = tid; i < 512 * 32; i += 256) {
        int j = i >> 5, q = i & 31;
        float4 v = ((const float4*)g_wcomb)[i];
        *(u64*)(smem + SM_B + (j * ATT_LDA + q * 4) * 2) = pack_bf16x4(v.x, v.y, v.z, v.w);
    }
    for (int i = tid; i < 512; i += 256) {
        ((float*)(smem + SM_B1))[i] = B1[i];
        ((float*)(smem + SM_W2))[i] = W2[i];
    }

    // async A-tile stager: 128 rows x 256B via 16B cp.async chunks
    auto stage = [&](int t, int bf) {
        if (t < TILES_TOTAL) {
            int rel = t / NTILES;
            int base = (t - rel * NTILES) * 128;
            const char* srcb = (const char*)g_aggh + (size_t)rel * NN * 256;
#pragma unroll
            for (int k2 = 0; k2 < 8; k2++) {
                int i = tid + k2 * 256;
                int row = i >> 4, q = i & 15;
                int node = base + row;
                bool vld = node < NN;
                const char* src = srcb + (size_t)(vld ? node : 0) * 256 + q * 16;
                u32 dsta = sb + SM_A0 + bf * A_BYTES + row * 272 + q * 16;
                int ss = vld ? 16 : 0;
                asm volatile("cp.async.cg.shared.global [%0], [%1], 16, %2;"
                             :: "r"(dsta), "l"(src), "r"(ss) : "memory");
            }
        }
        asm volatile("cp.async.commit_group;" ::: "memory");
    };

    stage(blockIdx.x, 0);
    __syncthreads();

    const float* b1s = (const float*)(smem + SM_B1);
    const float* w2s = (const float*)(smem + SM_W2);

    // Per-thread tile-invariant half2 bias/weight pairs for the epilogue
    __half2 bh[8], wh[8];
#pragma unroll
    for (int nn = 0; nn < 8; nn++) {
        int j0 = (wid << 6) + nn * 8 + ((lane & 3) << 1);
        bh[nn] = __floats2half2_rn(b1s[j0], b1s[j0 + 1]);
        wh[nn] = __floats2half2_rn(w2s[j0], w2s[j0 + 1]);
    }

    float racc[3] = {0.f, 0.f, 0.f};
    int buf = 0;

    for (int t = blockIdx.x; t < TILES_TOTAL; t += gridDim.x) {
        asm volatile("cp.async.wait_group 0;" ::: "memory");
        __syncthreads();
        stage(t + gridDim.x, buf ^ 1);   // overlap next tile load with compute

        int rel = t / NTILES;
        int base = (t - rel * NTILES) * 128;
        u32 abase = sb + SM_A0 + buf * A_BYTES;

        float ps = 0.f;
#pragma unroll
        for (int mp = 0; mp < 4; mp++) {
            int m0 = mp * 32;
            float acc[2][8][4];
#pragma unroll
            for (int s = 0; s < 2; s++)
#pragma unroll
                for (int n = 0; n < 8; n++)
#pragma unroll
                    for (int ee = 0; ee < 4; ee++) acc[s][n][ee] = 0.f;

#pragma unroll
            for (int kk = 0; kk < 8; kk++) {
                u32 a0[4], a1[4];
                u32 arow0 = m0 + (lane & 15);
                u32 acol = kk * 16 + ((lane >> 4) << 3);
                ldsm_x4(a0[0], a0[1], a0[2], a0[3], abase + (arow0 * ATT_LDA + acol) * 2);
                ldsm_x4(a1[0], a1[1], a1[2], a1[3],
                        abase + ((arow0 + 16) * ATT_LDA + acol) * 2);

                u32 grp = lane >> 3, l3 = lane & 7;
#pragma unroll
                for (int np = 0; np < 4; np++) {
                    // x4 B load: two n-groups (np*16 .. np*16+15) at once
                    u32 b0, b1r, b2, b3;
                    u32 brow = (wid << 6) + np * 16 + ((grp >> 1) << 3) + l3;
                    u32 bcol = kk * 16 + ((grp & 1) << 3);
                    ldsm_x4(b0, b1r, b2, b3, sb + SM_B + (brow * ATT_LDA + bcol) * 2);
                    mma_16816(acc[0][np * 2], a0[0], a0[1], a0[2], a0[3], b0, b1r);
                    mma_16816(acc[1][np * 2], a1[0], a1[1], a1[2], a1[3], b0, b1r);
                    mma_16816(acc[0][np * 2 + 1], a0[0], a0[1], a0[2], a0[3], b2, b3);
                    mma_16816(acc[1][np * 2 + 1], a1[0], a1[1], a1[2], a1[3], b2, b3);
                }
            }

            // Epilogue (f16x2): hsum += wh * tanh(acc + bh), masked on node validity
            __half2 hsum = __floats2half2_rn(0.f, 0.f);
            bool v0 = (base + m0 + (lane >> 2)) < NN;
            bool v1 = (base + m0 + 8 + (lane >> 2)) < NN;
            bool v2 = (base + m0 + 16 + (lane >> 2)) < NN;
            bool v3 = (base + m0 + 24 + (lane >> 2)) < NN;
#pragma unroll
            for (int nn = 0; nn < 8; nn++) {
#pragma unroll
                for (int s = 0; s < 2; s++) {
                    const float* c = acc[s][nn];
                    bool pa = s ? v2 : v0;
                    bool pb = s ? v3 : v1;
                    if (pa) {
                        __half2 x = __hadd2(__floats2half2_rn(c[0], c[1]), bh[nn]);
                        hsum = __hfma2(tanh2(x), wh[nn], hsum);
                    }
                    if (pb) {
                        __half2 x = __hadd2(__floats2half2_rn(c[2], c[3]), bh[nn]);
                        hsum = __hfma2(tanh2(x), wh[nn], hsum);
                    }
                }
            }
            float2 hs = __half22float2(hsum);
            ps += hs.x + hs.y;
        }
        racc[rel] += ps;
        buf ^= 1;
    }

#pragma unroll
    for (int o = 16; o; o >>= 1) {
        racc[0] += __shfl_xor_sync(0xffffffffu, racc[0], o);
        racc[1] += __shfl_xor_sync(0xffffffffu, racc[1], o);
        racc[2] += __shfl_xor_sync(0xffffffffu, racc[2], o);
    }
    if (lane == 0) {
        atomicAdd(&g_wsum[0], racc[0]);
        atomicAdd(&g_wsum[1], racc[1]);
        atomicAdd(&g_wsum[2], racc[2]);
    }
}

// ---------------- kernel: fuse = leaky((b0*geo + b1*trans + b2*cat) @ Wt^T) ------------
__global__ __launch_bounds__(256) void fuse_kernel(const float* __restrict__ Wt,
                                                   float* __restrict__ out) {
    extern __shared__ char smem[];
    float* Ws = (float*)smem;                  // 65536 B
    u64* Zs = (u64*)(smem + 65536);            // 32768 B
    int tid = threadIdx.x;
    stage_w128(Ws, Wt, tid, 256);
    __syncthreads();

    float w0 = g_wsum[0] * (1.f / NN);
    float w1 = g_wsum[1] * (1.f / NN);
    float w2 = g_wsum[2] * (1.f / NN);
    float m = fmaxf(w0, fmaxf(w1, w2));
    float e0 = expf(w0 - m), e1 = expf(w1 - m), e2 = expf(w2 - m);
    float inv = 1.f / (e0 + e1 + e2);
    float b0 = e0 * inv, b1 = e1 * inv, b2 = e2 * inv;

    const ulonglong2* Wv = (const ulonglong2*)Ws;
    int warp = tid >> 5, lane = tid & 31;
    u64* Zw = Zs + warp * 4 * DD;
    const float4* geo4 = (const float4*)g_agg;
    const float4* trn4 = geo4 + (size_t)NN * 32;
    const float4* cat4 = trn4 + (size_t)NN * 32;

    for (int base = blockIdx.x * 32 + warp * 4; base < NN; base += gridDim.x * 32) {
#pragma unroll
        for (int mm = 0; mm < 4; mm++) {
            int n = base + mm;
            float4 v = make_float4(0.f, 0.f, 0.f, 0.f);
            if (n < NN) {
                float4 g = geo4[(size_t)n * 32 + lane];
                float4 t = trn4[(size_t)n * 32 + lane];
                float4 c = cat4[(size_t)n * 32 + lane];
                v.x = b0 * g.x + b1 * t.x + b2 * c.x;
                v.y = b0 * g.y + b1 * t.y + b2 * c.y;
                v.z = b0 * g.z + b1 * t.z + b2 * c.z;
                v.w = b0 * g.w + b1 * t.w + b2 * c.w;
            }
            u64* zp = Zw + mm * DD + lane * 4;
            zp[0] = pack2(v.x); zp[1] = pack2(v.y); zp[2] = pack2(v.z); zp[3] = pack2(v.w);
        }
        __syncwarp();

        u64 acc[4][2];
#pragma unroll
        for (int mm = 0; mm < 4; mm++) { acc[mm][0] = 0ull; acc[mm][1] = 0ull; }

#pragma unroll 4
        for (int k = 0; k < DD; k++) {
            ulonglong2 wv = Wv[k * 32 + lane];
#pragma unroll
            for (int mm = 0; mm < 4; mm++) {
                u64 zz = Zw[mm * DD + k];
                ffma2(acc[mm][0], zz, wv.x);
                ffma2(acc[mm][1], zz, wv.y);
            }
        }

#pragma unroll
        for (int mm = 0; mm < 4; mm++) {
            int n = base + mm;
            if (n < NN) {
                float2 p0 = unpack2(acc[mm][0]);
                float2 p1 = unpack2(acc[mm][1]);
                p0.x = (p0.x >= 0.f) ? p0.x : 0.2f * p0.x;
                p0.y = (p0.y >= 0.f) ? p0.y : 0.2f * p0.y;
                p1.x = (p1.x >= 0.f) ? p1.x : 0.2f * p1.x;
                p1.y = (p1.y >= 0.f) ? p1.y : 0.2f * p1.y;
                ((float2*)out)[n * 64 + lane] = p0;
                ((float2*)out)[n * 64 + 32 + lane] = p1;
            }
        }
        __syncwarp();
    }
}

// ---------------- launcher -------------------------------------------------------------
extern "C" void kernel_launch(void* const* d_in, const int* in_sizes, int n_in,
                              void* d_out, int out_size) {
    const float* feat = (const float*)d_in[0];
    const float* Wt   = (const float*)d_in[1];
    const float* w1   = (const float*)d_in[2];
    const float* b1   = (const float*)d_in[3];
    const float* w2   = (const float*)d_in[4];
    const float* tw   = (const float*)d_in[5];
    const int* gs = (const int*)d_in[6];
    const int* gd = (const int*)d_in[7];
    const int* cs = (const int*)d_in[8];
    const int* cd = (const int*)d_in[9];
    const int* ts = (const int*)d_in[10];
    const int* td = (const int*)d_in[11];
    float* out = (float*)d_out;

    const int SMEM_FUSE = 65536 + 32768;
    cudaFuncSetAttribute(att_mma_kernel, cudaFuncAttributeMaxDynamicSharedMemorySize, SMEM_ATT);
    cudaFuncSetAttribute(fuse_kernel, cudaFuncAttributeMaxDynamicSharedMemorySize, SMEM_FUSE);

    zero_kernel<<<(3 * NN + 255) / 256, 256>>>();
    wcomb_kernel<<<256, 256>>>(w1, Wt);
    fill_kernel<<<(3 * NE + 255) / 256, 256>>>(gs, gd, cs, cd, ts, td, tw);
    gather_kernel<<<1184, 256>>>(feat);
    fixup_kernel<<<1, 256>>>(feat);
    att_mma_kernel<<<148, 256, SMEM_ATT>>>(b1, w2);
    fuse_kernel<<<296, 256, SMEM_FUSE>>>(Wt, out);
}